// round 5
// baseline (speedup 1.0000x reference)
#include <cuda_runtime.h>
#include <math.h>

#define Bsz  4
#define Tn   2048
#define Dm   768
#define Hn   12
#define HDm  64
#define MLPD 3072
#define WIN  256
#define NT   (Bsz * Tn)   /* 8192 rows */

// ---------------- static scratch (no runtime allocation allowed) ----------------
__device__ float g_xn  [NT * Dm];        // normalized activations (reused for ln1/ln2)
__device__ float g_qkv [NT * 3 * Dm];    // qkv projection
__device__ float g_attn[NT * Dm];        // attention output (heads merged)
__device__ float g_x1  [NT * Dm];        // residual after attention
__device__ float g_h   [NT * MLPD];      // MLP hidden

// ---------------- LayerNorm: one block per row ----------------
__global__ void __launch_bounds__(256) ln_kernel(const float* __restrict__ x,
                                                 const float* __restrict__ g,
                                                 const float* __restrict__ b,
                                                 float* __restrict__ y)
{
    const int row = blockIdx.x;
    const float* xr = x + (size_t)row * Dm;
    float* yr = y + (size_t)row * Dm;
    const int t = threadIdx.x;

    float v[3];
    float s = 0.f, s2 = 0.f;
#pragma unroll
    for (int i = 0; i < 3; i++) {
        v[i] = xr[t + i * 256];
        s += v[i];
        s2 += v[i] * v[i];
    }
    __shared__ float red[16];
#pragma unroll
    for (int o = 16; o > 0; o >>= 1) {
        s  += __shfl_xor_sync(0xffffffffu, s,  o);
        s2 += __shfl_xor_sync(0xffffffffu, s2, o);
    }
    const int w = t >> 5;
    if ((t & 31) == 0) { red[w] = s; red[8 + w] = s2; }
    __syncthreads();
    s = 0.f; s2 = 0.f;
#pragma unroll
    for (int i = 0; i < 8; i++) { s += red[i]; s2 += red[8 + i]; }

    const float mean = s * (1.0f / Dm);
    float var = s2 * (1.0f / Dm) - mean * mean;
    var = fmaxf(var, 0.0f);
    const float rstd = rsqrtf(var + 1e-5f);
#pragma unroll
    for (int i = 0; i < 3; i++) {
        const int c = t + i * 256;
        yr[c] = (v[i] - mean) * rstd * g[c] + b[c];
    }
}

// ---------------- SGEMM: C[M,N] = A[M,K] @ B[N,K]^T + bias (+res) (+gelu) ----------------
// 128x128 block tile, K-step 8, 256 threads, 8x8 micro-tile per thread.
// All dims are multiples of tile sizes for this problem -> no bounds checks.
template<int GELU, int RES>
__global__ void __launch_bounds__(256) gemm_kernel(
    const float* __restrict__ A,
    const float* __restrict__ B,
    const float* __restrict__ bias,
    const float* __restrict__ res,
    float* __restrict__ C,
    int M, int N, int K)
{
    __shared__ float As[8][128];
    __shared__ float Bs[8][128];

    const int bm = blockIdx.y * 128;
    const int bn = blockIdx.x * 128;
    const int t  = threadIdx.x;
    const int tx = t & 15;
    const int ty = t >> 4;
    const int lrow = t >> 1;          // 0..127
    const int lseg = (t & 1) << 2;    // 0 or 4

    const float* Ap = A + (size_t)(bm + lrow) * K + lseg;
    const float* Bp = B + (size_t)(bn + lrow) * K + lseg;

    float acc[8][8];
#pragma unroll
    for (int i = 0; i < 8; i++)
#pragma unroll
        for (int j = 0; j < 8; j++) acc[i][j] = 0.f;

    for (int k0 = 0; k0 < K; k0 += 8) {
        const float4 av = *(const float4*)(Ap + k0);
        const float4 bv = *(const float4*)(Bp + k0);
        __syncthreads();
        As[lseg + 0][lrow] = av.x; As[lseg + 1][lrow] = av.y;
        As[lseg + 2][lrow] = av.z; As[lseg + 3][lrow] = av.w;
        Bs[lseg + 0][lrow] = bv.x; Bs[lseg + 1][lrow] = bv.y;
        Bs[lseg + 2][lrow] = bv.z; Bs[lseg + 3][lrow] = bv.w;
        __syncthreads();
#pragma unroll
        for (int kk = 0; kk < 8; kk++) {
            float ar[8], br[8];
            *(float4*)&ar[0] = *(const float4*)&As[kk][ty * 4];
            *(float4*)&ar[4] = *(const float4*)&As[kk][64 + ty * 4];
            *(float4*)&br[0] = *(const float4*)&Bs[kk][tx * 4];
            *(float4*)&br[4] = *(const float4*)&Bs[kk][64 + tx * 4];
#pragma unroll
            for (int i = 0; i < 8; i++)
#pragma unroll
                for (int j = 0; j < 8; j++)
                    acc[i][j] = fmaf(ar[i], br[j], acc[i][j]);
        }
    }

    // epilogue
#pragma unroll
    for (int i = 0; i < 8; i++) {
        const int r = bm + ((i < 4) ? (ty * 4 + i) : (64 + ty * 4 + i - 4));
        const size_t roff = (size_t)r * N;
#pragma unroll
        for (int jh = 0; jh < 2; jh++) {
            const int c = bn + ((jh == 0) ? (tx * 4) : (64 + tx * 4));
            float4 o;
#pragma unroll
            for (int jj = 0; jj < 4; jj++) {
                float vv = acc[i][jh * 4 + jj] + bias[c + jj];
                if (RES)  vv += res[roff + c + jj];
                if (GELU) vv = 0.5f * vv * (1.0f + erff(vv * 0.70710678118654752f));
                (&o.x)[jj] = vv;
            }
            *(float4*)(C + roff + c) = o;
        }
    }
}

// ---------------- banded flash attention ----------------
// grid: (T/64, H, B); 256 threads. Q tile 64x64, K/V tiles of 64 keys.
// qkv layout: row (b*T + t), 2304 cols: [q(768) | k(768) | v(768)], head h at h*64.
__global__ void __launch_bounds__(256) attn_kernel(const float* __restrict__ qkv,
                                                   float* __restrict__ out)
{
    extern __shared__ float sm[];
    float* Qs = sm;                  // [64][68] transposed: Qs[d*68 + q]
    float* Ks = sm + 64 * 68;        // [64][68] transposed: Ks[d*68 + k]
    float* Vs = Ks + 64 * 68;        // [64][64] natural:    Vs[k*64 + d]
    float* Ps = Vs + 64 * 64;        // [64][64]

    const int qs = blockIdx.x * 64;
    const int h  = blockIdx.y;
    const int b  = blockIdx.z;
    const int t  = threadIdx.x;
    const int tx = t & 15;
    const int ty = t >> 4;

    const size_t rstride = 3 * Dm;   // 2304
    const float* base = qkv + (size_t)b * Tn * rstride + h * HDm;

    // load Q (transposed, pre-scaled by 1/sqrt(64))
#pragma unroll
    for (int i = 0; i < 4; i++) {
        const int lin = t + i * 256;
        const int r   = lin >> 4;
        const int c4  = (lin & 15) << 2;
        const float4 v = *(const float4*)(base + (size_t)(qs + r) * rstride + c4);
        Qs[(c4 + 0) * 68 + r] = v.x * 0.125f;
        Qs[(c4 + 1) * 68 + r] = v.y * 0.125f;
        Qs[(c4 + 2) * 68 + r] = v.z * 0.125f;
        Qs[(c4 + 3) * 68 + r] = v.w * 0.125f;
    }

    float m[4], l[4], o[4][4];
#pragma unroll
    for (int i = 0; i < 4; i++) {
        m[i] = -1e30f; l[i] = 0.f;
#pragma unroll
        for (int j = 0; j < 4; j++) o[i][j] = 0.f;
    }

    int kt0 = qs - WIN; if (kt0 < 0) kt0 = 0;
    int kt1 = qs + 64 + WIN; if (kt1 > Tn) kt1 = Tn;

    for (int kt = kt0; kt < kt1; kt += 64) {
        __syncthreads();
        // load K (transposed) and V (natural)
#pragma unroll
        for (int i = 0; i < 4; i++) {
            const int lin = t + i * 256;
            const int r   = lin >> 4;
            const int c4  = (lin & 15) << 2;
            const float* kr = base + (size_t)(kt + r) * rstride;
            const float4 kv = *(const float4*)(kr + Dm + c4);
            Ks[(c4 + 0) * 68 + r] = kv.x;
            Ks[(c4 + 1) * 68 + r] = kv.y;
            Ks[(c4 + 2) * 68 + r] = kv.z;
            Ks[(c4 + 3) * 68 + r] = kv.w;
            *(float4*)(Vs + r * 64 + c4) = *(const float4*)(kr + 2 * Dm + c4);
        }
        __syncthreads();

        // S = Q K^T (scaled) : 4x4 per thread
        float s[4][4];
#pragma unroll
        for (int i = 0; i < 4; i++)
#pragma unroll
            for (int j = 0; j < 4; j++) s[i][j] = 0.f;
#pragma unroll 8
        for (int kk = 0; kk < 64; kk++) {
            float aq[4], ak[4];
            *(float4*)aq = *(const float4*)(Qs + kk * 68 + ty * 4);
            *(float4*)ak = *(const float4*)(Ks + kk * 68 + tx * 4);
#pragma unroll
            for (int i = 0; i < 4; i++)
#pragma unroll
                for (int j = 0; j < 4; j++)
                    s[i][j] = fmaf(aq[i], ak[j], s[i][j]);
        }

        // band mask + online softmax (row group = 16 lanes sharing ty)
        float p[4][4];
#pragma unroll
        for (int i = 0; i < 4; i++) {
            const int qg = qs + ty * 4 + i;
            float tmax = -1e30f;
#pragma unroll
            for (int j = 0; j < 4; j++) {
                const int kg = kt + tx * 4 + j;
                const int dd = qg - kg;
                if (dd > WIN || dd < -WIN) s[i][j] = -1e30f;
                tmax = fmaxf(tmax, s[i][j]);
            }
#pragma unroll
            for (int ofs = 8; ofs > 0; ofs >>= 1)
                tmax = fmaxf(tmax, __shfl_xor_sync(0xffffffffu, tmax, ofs));
            const float mn = fmaxf(m[i], tmax);
            const float f  = expf(m[i] - mn);
            float sum = 0.f;
#pragma unroll
            for (int j = 0; j < 4; j++) {
                p[i][j] = expf(s[i][j] - mn);
                sum += p[i][j];
            }
#pragma unroll
            for (int ofs = 8; ofs > 0; ofs >>= 1)
                sum += __shfl_xor_sync(0xffffffffu, sum, ofs);
            l[i] = l[i] * f + sum;
            m[i] = mn;
#pragma unroll
            for (int j = 0; j < 4; j++) o[i][j] *= f;
        }
        // stage P
#pragma unroll
        for (int i = 0; i < 4; i++)
            *(float4*)(Ps + (ty * 4 + i) * 64 + tx * 4) =
                make_float4(p[i][0], p[i][1], p[i][2], p[i][3]);
        __syncthreads();

        // O += P @ V
#pragma unroll 2
        for (int kk = 0; kk < 64; kk += 4) {
            float4 pv[4];
#pragma unroll
            for (int i = 0; i < 4; i++)
                pv[i] = *(const float4*)(Ps + (ty * 4 + i) * 64 + kk);
#pragma unroll
            for (int u = 0; u < 4; u++) {
                float vv[4];
                *(float4*)vv = *(const float4*)(Vs + (kk + u) * 64 + tx * 4);
#pragma unroll
                for (int i = 0; i < 4; i++) {
                    const float pu = (&pv[i].x)[u];
#pragma unroll
                    for (int j = 0; j < 4; j++)
                        o[i][j] = fmaf(pu, vv[j], o[i][j]);
                }
            }
        }
    }

    // write normalized output back to merged-head layout
#pragma unroll
    for (int i = 0; i < 4; i++) {
        const float inv = 1.0f / l[i];
        const float4 ov = make_float4(o[i][0] * inv, o[i][1] * inv,
                                      o[i][2] * inv, o[i][3] * inv);
        *(float4*)(out + (size_t)((size_t)b * Tn + qs + ty * 4 + i) * Dm
                       + h * HDm + tx * 4) = ov;
    }
}

// ---------------- launch ----------------
extern "C" void kernel_launch(void* const* d_in, const int* in_sizes, int n_in,
                              void* d_out, int out_size)
{
    const float* x    = (const float*)d_in[0];
    const float* in_w = (const float*)d_in[1];
    const float* in_b = (const float*)d_in[2];
    const float* ow   = (const float*)d_in[3];
    const float* ob   = (const float*)d_in[4];
    const float* w1   = (const float*)d_in[5];
    const float* b1   = (const float*)d_in[6];
    const float* w2   = (const float*)d_in[7];
    const float* b2   = (const float*)d_in[8];
    const float* ln1g = (const float*)d_in[9];
    const float* ln1b = (const float*)d_in[10];
    const float* ln2g = (const float*)d_in[11];
    const float* ln2b = (const float*)d_in[12];
    float* out = (float*)d_out;

    float *xn, *qkv, *attn, *x1, *hbuf;
    cudaGetSymbolAddress((void**)&xn,   g_xn);
    cudaGetSymbolAddress((void**)&qkv,  g_qkv);
    cudaGetSymbolAddress((void**)&attn, g_attn);
    cudaGetSymbolAddress((void**)&x1,   g_x1);
    cudaGetSymbolAddress((void**)&hbuf, g_h);

    const size_t attn_smem = (size_t)(2 * 64 * 68 + 2 * 64 * 64) * sizeof(float); // 67584 B
    cudaFuncSetAttribute(attn_kernel, cudaFuncAttributeMaxDynamicSharedMemorySize,
                         (int)attn_smem);

    // 1) LN1
    ln_kernel<<<NT, 256>>>(x, ln1g, ln1b, xn);
    // 2) QKV projection
    gemm_kernel<0, 0><<<dim3(3 * Dm / 128, NT / 128), 256>>>(
        xn, in_w, in_b, nullptr, qkv, NT, 3 * Dm, Dm);
    // 3) banded attention
    attn_kernel<<<dim3(Tn / 64, Hn, Bsz), 256, attn_smem>>>(qkv, attn);
    // 4) out projection + residual
    gemm_kernel<0, 1><<<dim3(Dm / 128, NT / 128), 256>>>(
        attn, ow, ob, x, x1, NT, Dm, Dm);
    // 5) LN2
    ln_kernel<<<NT, 256>>>(x1, ln2g, ln2b, xn);
    // 6) MLP up + exact GELU
    gemm_kernel<1, 0><<<dim3(MLPD / 128, NT / 128), 256>>>(
        xn, w1, b1, nullptr, hbuf, NT, MLPD, Dm);
    // 7) MLP down + residual -> d_out
    gemm_kernel<0, 1><<<dim3(Dm / 128, NT / 128), 256>>>(
        hbuf, w2, b2, x1, out, NT, Dm, MLPD);
}

// round 6
// speedup vs baseline: 1.0762x; 1.0762x over previous
#include <cuda_runtime.h>
#include <math.h>
#include <stdint.h>

#define Bsz  4
#define Tn   2048
#define Dm   768
#define Hn   12
#define HDm  64
#define MLPD 3072
#define WIN  256
#define NT   (Bsz * Tn)   /* 8192 rows */

// ---------------- static scratch (no runtime allocation allowed) ----------------
__device__ float g_xn  [NT * Dm];        // normalized activations (reused for ln1/ln2)
__device__ float g_qkv [NT * 3 * Dm];    // qkv projection
__device__ float g_attn[NT * Dm];        // attention output (heads merged)
__device__ float g_x1  [NT * Dm];        // residual after attention
__device__ float g_h   [NT * MLPD];      // MLP hidden

// ---------------- LayerNorm: one block per row ----------------
__global__ void __launch_bounds__(256) ln_kernel(const float* __restrict__ x,
                                                 const float* __restrict__ g,
                                                 const float* __restrict__ b,
                                                 float* __restrict__ y)
{
    const int row = blockIdx.x;
    const float* xr = x + (size_t)row * Dm;
    float* yr = y + (size_t)row * Dm;
    const int t = threadIdx.x;

    float v[3];
    float s = 0.f, s2 = 0.f;
#pragma unroll
    for (int i = 0; i < 3; i++) {
        v[i] = xr[t + i * 256];
        s += v[i];
        s2 += v[i] * v[i];
    }
    __shared__ float red[16];
#pragma unroll
    for (int o = 16; o > 0; o >>= 1) {
        s  += __shfl_xor_sync(0xffffffffu, s,  o);
        s2 += __shfl_xor_sync(0xffffffffu, s2, o);
    }
    const int w = t >> 5;
    if ((t & 31) == 0) { red[w] = s; red[8 + w] = s2; }
    __syncthreads();
    s = 0.f; s2 = 0.f;
#pragma unroll
    for (int i = 0; i < 8; i++) { s += red[i]; s2 += red[8 + i]; }

    const float mean = s * (1.0f / Dm);
    float var = s2 * (1.0f / Dm) - mean * mean;
    var = fmaxf(var, 0.0f);
    const float rstd = rsqrtf(var + 1e-5f);
#pragma unroll
    for (int i = 0; i < 3; i++) {
        const int c = t + i * 256;
        yr[c] = (v[i] - mean) * rstd * g[c] + b[c];
    }
}

// ---------------- tf32 tensor-core GEMM ----------------
// C[M,N] = A[M,K] @ B[N,K]^T + bias (+res) (+gelu)
// 128x128 block tile, BK=16, 256 threads = 8 warps, warp tile 32(M) x 64(N).
// mma.sync.m16n8k8.tf32 with rna-rounded operands.
// Smem layout permuted so fragment loads are conflict-free LDS.128:
//   value (k, m) stored at smem[k][ (m%8)*16 + m/8 ]  (row padded to 132)

__device__ __forceinline__ uint32_t f2tf(float f) {
    uint32_t r;
    asm("cvt.rna.tf32.f32 %0, %1;" : "=r"(r) : "f"(f));
    return r;
}

#define MMA_TF32(c, A0, A1, A2, A3, B0, B1)                              \
    asm volatile(                                                        \
        "mma.sync.aligned.m16n8k8.row.col.f32.tf32.tf32.f32 "            \
        "{%0,%1,%2,%3}, {%4,%5,%6,%7}, {%8,%9}, {%0,%1,%2,%3};"          \
        : "+f"((c)[0]), "+f"((c)[1]), "+f"((c)[2]), "+f"((c)[3])         \
        : "r"(A0), "r"(A1), "r"(A2), "r"(A3), "r"(B0), "r"(B1))

template<int GELU, int RES>
__global__ void __launch_bounds__(256) gemm_tf32_kernel(
    const float* __restrict__ A,
    const float* __restrict__ B,
    const float* __restrict__ bias,
    const float* __restrict__ res,
    float* __restrict__ C,
    int M, int N, int K)
{
    __shared__ uint32_t As[2][16][132];
    __shared__ uint32_t Bs[2][16][132];

    const int t    = threadIdx.x;
    const int lane = t & 31;
    const int warp = t >> 5;
    const int wM   = warp & 3;     // 4 M-warps * 32 = 128
    const int wN   = warp >> 2;    // 2 N-warps * 64 = 128
    const int g    = lane >> 2;    // 0..7
    const int l4   = lane & 3;     // 0..3
    const int bm   = blockIdx.y * 128;
    const int bn   = blockIdx.x * 128;

    // gmem->smem mapping: thread handles rows rA and rA+64, k cols kA..kA+3
    const int rA = t >> 2;
    const int kA = (t & 3) * 4;
    const float* Ap = A + (size_t)(bm + rA) * K + kA;
    const float* Bp = B + (size_t)(bn + rA) * K + kA;
    const size_t half = (size_t)64 * K;
    const int sc = (rA & 7) * 16 + (rA >> 3);   // permuted store column (rows 0..63)

    float c[2][8][4];
#pragma unroll
    for (int i = 0; i < 2; i++)
#pragma unroll
        for (int j = 0; j < 8; j++)
#pragma unroll
            for (int q = 0; q < 4; q++) c[i][j][q] = 0.f;

    float4 ra0, ra1, rb0, rb1;
    ra0 = *(const float4*)(Ap);
    ra1 = *(const float4*)(Ap + half);
    rb0 = *(const float4*)(Bp);
    rb1 = *(const float4*)(Bp + half);

    auto store_tile = [&](int buf) {
#pragma unroll
        for (int d = 0; d < 4; d++) {
            As[buf][kA + d][sc]     = f2tf((&ra0.x)[d]);
            As[buf][kA + d][sc + 8] = f2tf((&ra1.x)[d]);
            Bs[buf][kA + d][sc]     = f2tf((&rb0.x)[d]);
            Bs[buf][kA + d][sc + 8] = f2tf((&rb1.x)[d]);
        }
    };
    store_tile(0);
    __syncthreads();

    const int ntiles = K / 16;
    for (int tile = 0; tile < ntiles; tile++) {
        const int buf = tile & 1;
        if (tile + 1 < ntiles) {
            const float* Ap2 = Ap + (tile + 1) * 16;
            const float* Bp2 = Bp + (tile + 1) * 16;
            ra0 = *(const float4*)(Ap2);
            ra1 = *(const float4*)(Ap2 + half);
            rb0 = *(const float4*)(Bp2);
            rb1 = *(const float4*)(Bp2 + half);
        }
#pragma unroll
        for (int ks = 0; ks < 2; ks++) {
            const uint32_t* ap = &As[buf][ks * 8 + l4][g * 16 + wM * 4];
            const uint32_t* bp = &Bs[buf][ks * 8 + l4][g * 16 + wN * 8];
            const uint4 aLo = *(const uint4*)ap;
            const uint4 aHi = *(const uint4*)(ap + 4 * 132);
            const uint4 b0a = *(const uint4*)bp;
            const uint4 b0b = *(const uint4*)(bp + 4);
            const uint4 b1a = *(const uint4*)(bp + 4 * 132);
            const uint4 b1b = *(const uint4*)(bp + 4 * 132 + 4);

            const uint32_t A0[2] = {aLo.x, aLo.z};
            const uint32_t A1[2] = {aLo.y, aLo.w};
            const uint32_t A2[2] = {aHi.x, aHi.z};
            const uint32_t A3[2] = {aHi.y, aHi.w};
            const uint32_t B0[8] = {b0a.x, b0a.y, b0a.z, b0a.w,
                                    b0b.x, b0b.y, b0b.z, b0b.w};
            const uint32_t B1[8] = {b1a.x, b1a.y, b1a.z, b1a.w,
                                    b1b.x, b1b.y, b1b.z, b1b.w};
#pragma unroll
            for (int i = 0; i < 2; i++)
#pragma unroll
                for (int j = 0; j < 8; j++)
                    MMA_TF32(c[i][j], A0[i], A1[i], A2[i], A3[i], B0[j], B1[j]);
        }
        if (tile + 1 < ntiles) store_tile(buf ^ 1);
        __syncthreads();
    }

    // ---- epilogue ----
#pragma unroll
    for (int i = 0; i < 2; i++) {
        const int r0 = bm + wM * 32 + i * 16 + g;
#pragma unroll
        for (int j = 0; j < 8; j++) {
            const int col = bn + wN * 64 + j * 8 + l4 * 2;
            const float2 bia = *(const float2*)(bias + col);
            float v00 = c[i][j][0] + bia.x, v01 = c[i][j][1] + bia.y;
            float v10 = c[i][j][2] + bia.x, v11 = c[i][j][3] + bia.y;
            if (RES) {
                const float2 q0 = *(const float2*)(res + (size_t)r0 * N + col);
                const float2 q1 = *(const float2*)(res + (size_t)(r0 + 8) * N + col);
                v00 += q0.x; v01 += q0.y; v10 += q1.x; v11 += q1.y;
            }
            if (GELU) {
                v00 = 0.5f * v00 * (1.0f + erff(v00 * 0.70710678118654752f));
                v01 = 0.5f * v01 * (1.0f + erff(v01 * 0.70710678118654752f));
                v10 = 0.5f * v10 * (1.0f + erff(v10 * 0.70710678118654752f));
                v11 = 0.5f * v11 * (1.0f + erff(v11 * 0.70710678118654752f));
            }
            *(float2*)(C + (size_t)r0 * N + col)       = make_float2(v00, v01);
            *(float2*)(C + (size_t)(r0 + 8) * N + col) = make_float2(v10, v11);
        }
    }
}

// ---------------- banded flash attention (fp32) ----------------
__global__ void __launch_bounds__(256) attn_kernel(const float* __restrict__ qkv,
                                                   float* __restrict__ out)
{
    extern __shared__ float sm[];
    float* Qs = sm;                  // [64][68] transposed: Qs[d*68 + q]
    float* Ks = sm + 64 * 68;        // [64][68] transposed: Ks[d*68 + k]
    float* Vs = Ks + 64 * 68;        // [64][64] natural:    Vs[k*64 + d]
    float* Ps = Vs + 64 * 64;        // [64][64]

    const int qs = blockIdx.x * 64;
    const int h  = blockIdx.y;
    const int b  = blockIdx.z;
    const int t  = threadIdx.x;
    const int tx = t & 15;
    const int ty = t >> 4;

    const size_t rstride = 3 * Dm;   // 2304
    const float* base = qkv + (size_t)b * Tn * rstride + h * HDm;

#pragma unroll
    for (int i = 0; i < 4; i++) {
        const int lin = t + i * 256;
        const int r   = lin >> 4;
        const int c4  = (lin & 15) << 2;
        const float4 v = *(const float4*)(base + (size_t)(qs + r) * rstride + c4);
        Qs[(c4 + 0) * 68 + r] = v.x * 0.125f;
        Qs[(c4 + 1) * 68 + r] = v.y * 0.125f;
        Qs[(c4 + 2) * 68 + r] = v.z * 0.125f;
        Qs[(c4 + 3) * 68 + r] = v.w * 0.125f;
    }

    float m[4], l[4], o[4][4];
#pragma unroll
    for (int i = 0; i < 4; i++) {
        m[i] = -1e30f; l[i] = 0.f;
#pragma unroll
        for (int j = 0; j < 4; j++) o[i][j] = 0.f;
    }

    int kt0 = qs - WIN; if (kt0 < 0) kt0 = 0;
    int kt1 = qs + 64 + WIN; if (kt1 > Tn) kt1 = Tn;

    for (int kt = kt0; kt < kt1; kt += 64) {
        __syncthreads();
#pragma unroll
        for (int i = 0; i < 4; i++) {
            const int lin = t + i * 256;
            const int r   = lin >> 4;
            const int c4  = (lin & 15) << 2;
            const float* kr = base + (size_t)(kt + r) * rstride;
            const float4 kv = *(const float4*)(kr + Dm + c4);
            Ks[(c4 + 0) * 68 + r] = kv.x;
            Ks[(c4 + 1) * 68 + r] = kv.y;
            Ks[(c4 + 2) * 68 + r] = kv.z;
            Ks[(c4 + 3) * 68 + r] = kv.w;
            *(float4*)(Vs + r * 64 + c4) = *(const float4*)(kr + 2 * Dm + c4);
        }
        __syncthreads();

        float s[4][4];
#pragma unroll
        for (int i = 0; i < 4; i++)
#pragma unroll
            for (int j = 0; j < 4; j++) s[i][j] = 0.f;
#pragma unroll 8
        for (int kk = 0; kk < 64; kk++) {
            float aq[4], ak[4];
            *(float4*)aq = *(const float4*)(Qs + kk * 68 + ty * 4);
            *(float4*)ak = *(const float4*)(Ks + kk * 68 + tx * 4);
#pragma unroll
            for (int i = 0; i < 4; i++)
#pragma unroll
                for (int j = 0; j < 4; j++)
                    s[i][j] = fmaf(aq[i], ak[j], s[i][j]);
        }

        float p[4][4];
#pragma unroll
        for (int i = 0; i < 4; i++) {
            const int qg = qs + ty * 4 + i;
            float tmax = -1e30f;
#pragma unroll
            for (int j = 0; j < 4; j++) {
                const int kg = kt + tx * 4 + j;
                const int dd = qg - kg;
                if (dd > WIN || dd < -WIN) s[i][j] = -1e30f;
                tmax = fmaxf(tmax, s[i][j]);
            }
#pragma unroll
            for (int ofs = 8; ofs > 0; ofs >>= 1)
                tmax = fmaxf(tmax, __shfl_xor_sync(0xffffffffu, tmax, ofs));
            const float mn = fmaxf(m[i], tmax);
            const float f  = expf(m[i] - mn);
            float sum = 0.f;
#pragma unroll
            for (int j = 0; j < 4; j++) {
                p[i][j] = expf(s[i][j] - mn);
                sum += p[i][j];
            }
#pragma unroll
            for (int ofs = 8; ofs > 0; ofs >>= 1)
                sum += __shfl_xor_sync(0xffffffffu, sum, ofs);
            l[i] = l[i] * f + sum;
            m[i] = mn;
#pragma unroll
            for (int j = 0; j < 4; j++) o[i][j] *= f;
        }
#pragma unroll
        for (int i = 0; i < 4; i++)
            *(float4*)(Ps + (ty * 4 + i) * 64 + tx * 4) =
                make_float4(p[i][0], p[i][1], p[i][2], p[i][3]);
        __syncthreads();

#pragma unroll 2
        for (int kk = 0; kk < 64; kk += 4) {
            float4 pv[4];
#pragma unroll
            for (int i = 0; i < 4; i++)
                pv[i] = *(const float4*)(Ps + (ty * 4 + i) * 64 + kk);
#pragma unroll
            for (int u = 0; u < 4; u++) {
                float vv[4];
                *(float4*)vv = *(const float4*)(Vs + (kk + u) * 64 + tx * 4);
#pragma unroll
                for (int i = 0; i < 4; i++) {
                    const float pu = (&pv[i].x)[u];
#pragma unroll
                    for (int j = 0; j < 4; j++)
                        o[i][j] = fmaf(pu, vv[j], o[i][j]);
                }
            }
        }
    }

#pragma unroll
    for (int i = 0; i < 4; i++) {
        const float inv = 1.0f / l[i];
        const float4 ov = make_float4(o[i][0] * inv, o[i][1] * inv,
                                      o[i][2] * inv, o[i][3] * inv);
        *(float4*)(out + (size_t)((size_t)b * Tn + qs + ty * 4 + i) * Dm
                       + h * HDm + tx * 4) = ov;
    }
}

// ---------------- launch ----------------
extern "C" void kernel_launch(void* const* d_in, const int* in_sizes, int n_in,
                              void* d_out, int out_size)
{
    const float* x    = (const float*)d_in[0];
    const float* in_w = (const float*)d_in[1];
    const float* in_b = (const float*)d_in[2];
    const float* ow   = (const float*)d_in[3];
    const float* ob   = (const float*)d_in[4];
    const float* w1   = (const float*)d_in[5];
    const float* b1   = (const float*)d_in[6];
    const float* w2   = (const float*)d_in[7];
    const float* b2   = (const float*)d_in[8];
    const float* ln1g = (const float*)d_in[9];
    const float* ln1b = (const float*)d_in[10];
    const float* ln2g = (const float*)d_in[11];
    const float* ln2b = (const float*)d_in[12];
    float* out = (float*)d_out;

    float *xn, *qkv, *attn, *x1, *hbuf;
    cudaGetSymbolAddress((void**)&xn,   g_xn);
    cudaGetSymbolAddress((void**)&qkv,  g_qkv);
    cudaGetSymbolAddress((void**)&attn, g_attn);
    cudaGetSymbolAddress((void**)&x1,   g_x1);
    cudaGetSymbolAddress((void**)&hbuf, g_h);

    const size_t attn_smem = (size_t)(2 * 64 * 68 + 2 * 64 * 64) * sizeof(float); // 67584 B
    cudaFuncSetAttribute(attn_kernel, cudaFuncAttributeMaxDynamicSharedMemorySize,
                         (int)attn_smem);

    // 1) LN1
    ln_kernel<<<NT, 256>>>(x, ln1g, ln1b, xn);
    // 2) QKV projection (tf32 TC)
    gemm_tf32_kernel<0, 0><<<dim3(3 * Dm / 128, NT / 128), 256>>>(
        xn, in_w, in_b, nullptr, qkv, NT, 3 * Dm, Dm);
    // 3) banded attention
    attn_kernel<<<dim3(Tn / 64, Hn, Bsz), 256, attn_smem>>>(qkv, attn);
    // 4) out projection + residual (tf32 TC)
    gemm_tf32_kernel<0, 1><<<dim3(Dm / 128, NT / 128), 256>>>(
        attn, ow, ob, x, x1, NT, Dm, Dm);
    // 5) LN2
    ln_kernel<<<NT, 256>>>(x1, ln2g, ln2b, xn);
    // 6) MLP up + exact GELU (tf32 TC)
    gemm_tf32_kernel<1, 0><<<dim3(MLPD / 128, NT / 128), 256>>>(
        xn, w1, b1, nullptr, hbuf, NT, MLPD, Dm);
    // 7) MLP down + residual -> d_out (tf32 TC)
    gemm_tf32_kernel<0, 1><<<dim3(Dm / 128, NT / 128), 256>>>(
        hbuf, w2, b2, x1, out, NT, Dm, MLPD);
}

// round 8
// speedup vs baseline: 1.2873x; 1.1961x over previous
#include <cuda_runtime.h>
#include <math.h>
#include <stdint.h>

#define Bsz  4
#define Tn   2048
#define Dm   768
#define Hn   12
#define HDm  64
#define MLPD 3072
#define WIN  256
#define NT   (Bsz * Tn)   /* 8192 rows */

// ---------------- static scratch ----------------
__device__ float g_xn  [NT * Dm];
__device__ float g_qkv [NT * 3 * Dm];
__device__ float g_attn[NT * Dm];
__device__ float g_x1  [NT * Dm];
__device__ float g_h   [NT * MLPD];

// ---------------- LayerNorm ----------------
__global__ void __launch_bounds__(256) ln_kernel(const float* __restrict__ x,
                                                 const float* __restrict__ g,
                                                 const float* __restrict__ b,
                                                 float* __restrict__ y)
{
    const int row = blockIdx.x;
    const float* xr = x + (size_t)row * Dm;
    float* yr = y + (size_t)row * Dm;
    const int t = threadIdx.x;

    float v[3];
    float s = 0.f, s2 = 0.f;
#pragma unroll
    for (int i = 0; i < 3; i++) {
        v[i] = xr[t + i * 256];
        s += v[i];
        s2 += v[i] * v[i];
    }
    __shared__ float red[16];
#pragma unroll
    for (int o = 16; o > 0; o >>= 1) {
        s  += __shfl_xor_sync(0xffffffffu, s,  o);
        s2 += __shfl_xor_sync(0xffffffffu, s2, o);
    }
    const int w = t >> 5;
    if ((t & 31) == 0) { red[w] = s; red[8 + w] = s2; }
    __syncthreads();
    s = 0.f; s2 = 0.f;
#pragma unroll
    for (int i = 0; i < 8; i++) { s += red[i]; s2 += red[8 + i]; }

    const float mean = s * (1.0f / Dm);
    float var = s2 * (1.0f / Dm) - mean * mean;
    var = fmaxf(var, 0.0f);
    const float rstd = rsqrtf(var + 1e-5f);
#pragma unroll
    for (int i = 0; i < 3; i++) {
        const int c = t + i * 256;
        yr[c] = (v[i] - mean) * rstd * g[c] + b[c];
    }
}

// ---------------- tf32 tensor-core GEMM (mma.sync) ----------------
// C[M,N] = A[M,K] @ B[N,K]^T + bias (+res) (+gelu)
// 128x128 CTA tile, BK=16, 512 threads = 16 warps (4x4), warp tile 32x32.
// Permuted smem: value (k, m) at smem[k][(m%8)*16 + m/8], row padded to 132.
// Conflict-free STS via lane->(m,kq) remap; conflict-free LDS.128 fragments.

__device__ __forceinline__ uint32_t f2tf(float f) {
    uint32_t r;
    asm("cvt.rna.tf32.f32 %0, %1;" : "=r"(r) : "f"(f));
    return r;
}

#define MMA_TF32(c, A0, A1, A2, A3, B0, B1)                              \
    asm volatile(                                                        \
        "mma.sync.aligned.m16n8k8.row.col.f32.tf32.tf32.f32 "            \
        "{%0,%1,%2,%3}, {%4,%5,%6,%7}, {%8,%9}, {%0,%1,%2,%3};"          \
        : "+f"((c)[0]), "+f"((c)[1]), "+f"((c)[2]), "+f"((c)[3])         \
        : "r"(A0), "r"(A1), "r"(A2), "r"(A3), "r"(B0), "r"(B1))

template<int GELU, int RES>
__global__ void __launch_bounds__(512) gemm_tf32_kernel(
    const float* __restrict__ A,
    const float* __restrict__ B,
    const float* __restrict__ bias,
    const float* __restrict__ res,
    float* __restrict__ C,
    int M, int N, int K)
{
    __shared__ uint32_t As[2][16][132];
    __shared__ uint32_t Bs[2][16][132];

    const int t    = threadIdx.x;
    const int lane = t & 31;
    const int warp = t >> 5;        // 0..15
    const int wM   = warp & 3;      // 4 M-warps * 32 = 128
    const int wN   = warp >> 2;     // 4 N-warps * 32 = 128
    const int g    = lane >> 2;     // 0..7
    const int l4   = lane & 3;      // 0..3
    const int bm   = blockIdx.y * 128;
    const int bn   = blockIdx.x * 128;

    // gmem->smem mapping (conflict-free stores):
    // lane l, warp w: row = (l%16)*8 + (w%8), kq = l/16 + 2*(w/8)
    const int mrow = (lane & 15) * 8 + (warp & 7);
    const int kcol = ((lane >> 4) + 2 * (warp >> 3)) * 4;   // 0,4,8,12
    const int pcol = (warp & 7) * 16 + (lane & 15);         // perm(mrow)

    const float* Ap = A + (size_t)(bm + mrow) * K + kcol;
    const float* Bp = B + (size_t)(bn + mrow) * K + kcol;

    float c[2][4][4];
#pragma unroll
    for (int i = 0; i < 2; i++)
#pragma unroll
        for (int j = 0; j < 4; j++)
#pragma unroll
            for (int q = 0; q < 4; q++) c[i][j][q] = 0.f;

    float4 ra = *(const float4*)(Ap);
    float4 rb = *(const float4*)(Bp);

    auto store_tile = [&](int buf) {
#pragma unroll
        for (int d = 0; d < 4; d++) {
            As[buf][kcol + d][pcol] = f2tf((&ra.x)[d]);
            Bs[buf][kcol + d][pcol] = f2tf((&rb.x)[d]);
        }
    };
    store_tile(0);
    __syncthreads();

    const int ntiles = K / 16;
    for (int tile = 0; tile < ntiles; tile++) {
        const int buf = tile & 1;
        if (tile + 1 < ntiles) {
            ra = *(const float4*)(Ap + (tile + 1) * 16);
            rb = *(const float4*)(Bp + (tile + 1) * 16);
        }
#pragma unroll
        for (int ks = 0; ks < 2; ks++) {
            const uint32_t* ap = &As[buf][ks * 8 + l4][g * 16 + wM * 4];
            const uint32_t* bp = &Bs[buf][ks * 8 + l4][g * 16 + wN * 4];
            const uint4 aLo = *(const uint4*)ap;
            const uint4 aHi = *(const uint4*)(ap + 4 * 132);
            const uint4 bLo = *(const uint4*)bp;
            const uint4 bHi = *(const uint4*)(bp + 4 * 132);

            const uint32_t A0[2] = {aLo.x, aLo.z};
            const uint32_t A1[2] = {aLo.y, aLo.w};
            const uint32_t A2[2] = {aHi.x, aHi.z};
            const uint32_t A3[2] = {aHi.y, aHi.w};
            const uint32_t B0[4] = {bLo.x, bLo.y, bLo.z, bLo.w};
            const uint32_t B1[4] = {bHi.x, bHi.y, bHi.z, bHi.w};
#pragma unroll
            for (int i = 0; i < 2; i++)
#pragma unroll
                for (int j = 0; j < 4; j++)
                    MMA_TF32(c[i][j], A0[i], A1[i], A2[i], A3[i], B0[j], B1[j]);
        }
        if (tile + 1 < ntiles) store_tile(buf ^ 1);
        __syncthreads();
    }

    // ---- epilogue ----
#pragma unroll
    for (int i = 0; i < 2; i++) {
        const int r0 = bm + wM * 32 + i * 16 + g;
#pragma unroll
        for (int j = 0; j < 4; j++) {
            const int col = bn + wN * 32 + j * 8 + l4 * 2;
            const float2 bia = *(const float2*)(bias + col);
            float v00 = c[i][j][0] + bia.x, v01 = c[i][j][1] + bia.y;
            float v10 = c[i][j][2] + bia.x, v11 = c[i][j][3] + bia.y;
            if (RES) {
                const float2 q0 = *(const float2*)(res + (size_t)r0 * N + col);
                const float2 q1 = *(const float2*)(res + (size_t)(r0 + 8) * N + col);
                v00 += q0.x; v01 += q0.y; v10 += q1.x; v11 += q1.y;
            }
            if (GELU) {
                v00 = 0.5f * v00 * (1.0f + erff(v00 * 0.70710678118654752f));
                v01 = 0.5f * v01 * (1.0f + erff(v01 * 0.70710678118654752f));
                v10 = 0.5f * v10 * (1.0f + erff(v10 * 0.70710678118654752f));
                v11 = 0.5f * v11 * (1.0f + erff(v11 * 0.70710678118654752f));
            }
            *(float2*)(C + (size_t)r0 * N + col)       = make_float2(v00, v01);
            *(float2*)(C + (size_t)(r0 + 8) * N + col) = make_float2(v10, v11);
        }
    }
}

// ---------------- banded flash attention (fp32) ----------------
__global__ void __launch_bounds__(256) attn_kernel(const float* __restrict__ qkv,
                                                   float* __restrict__ out)
{
    extern __shared__ float sm[];
    float* Qs = sm;                  // [64][68] transposed
    float* Ks = sm + 64 * 68;        // [64][68] transposed
    float* Vs = Ks + 64 * 68;        // [64][64]
    float* Ps = Vs + 64 * 64;        // [64][64]

    const int qs = blockIdx.x * 64;
    const int h  = blockIdx.y;
    const int b  = blockIdx.z;
    const int t  = threadIdx.x;
    const int tx = t & 15;
    const int ty = t >> 4;

    const size_t rstride = 3 * Dm;
    const float* base = qkv + (size_t)b * Tn * rstride + h * HDm;

#pragma unroll
    for (int i = 0; i < 4; i++) {
        const int lin = t + i * 256;
        const int r   = lin >> 4;
        const int c4  = (lin & 15) << 2;
        const float4 v = *(const float4*)(base + (size_t)(qs + r) * rstride + c4);
        Qs[(c4 + 0) * 68 + r] = v.x * 0.125f;
        Qs[(c4 + 1) * 68 + r] = v.y * 0.125f;
        Qs[(c4 + 2) * 68 + r] = v.z * 0.125f;
        Qs[(c4 + 3) * 68 + r] = v.w * 0.125f;
    }

    float m[4], l[4], o[4][4];
#pragma unroll
    for (int i = 0; i < 4; i++) {
        m[i] = -1e30f; l[i] = 0.f;
#pragma unroll
        for (int j = 0; j < 4; j++) o[i][j] = 0.f;
    }

    int kt0 = qs - WIN; if (kt0 < 0) kt0 = 0;
    int kt1 = qs + 64 + WIN; if (kt1 > Tn) kt1 = Tn;

    for (int kt = kt0; kt < kt1; kt += 64) {
        __syncthreads();
#pragma unroll
        for (int i = 0; i < 4; i++) {
            const int lin = t + i * 256;
            const int r   = lin >> 4;
            const int c4  = (lin & 15) << 2;
            const float* kr = base + (size_t)(kt + r) * rstride;
            const float4 kv = *(const float4*)(kr + Dm + c4);
            Ks[(c4 + 0) * 68 + r] = kv.x;
            Ks[(c4 + 1) * 68 + r] = kv.y;
            Ks[(c4 + 2) * 68 + r] = kv.z;
            Ks[(c4 + 3) * 68 + r] = kv.w;
            *(float4*)(Vs + r * 64 + c4) = *(const float4*)(kr + 2 * Dm + c4);
        }
        __syncthreads();

        float s[4][4];
#pragma unroll
        for (int i = 0; i < 4; i++)
#pragma unroll
            for (int j = 0; j < 4; j++) s[i][j] = 0.f;
#pragma unroll 8
        for (int kk = 0; kk < 64; kk++) {
            float aq[4], ak[4];
            *(float4*)aq = *(const float4*)(Qs + kk * 68 + ty * 4);
            *(float4*)ak = *(const float4*)(Ks + kk * 68 + tx * 4);
#pragma unroll
            for (int i = 0; i < 4; i++)
#pragma unroll
                for (int j = 0; j < 4; j++)
                    s[i][j] = fmaf(aq[i], ak[j], s[i][j]);
        }

        float p[4][4];
#pragma unroll
        for (int i = 0; i < 4; i++) {
            const int qg = qs + ty * 4 + i;
            float tmax = -1e30f;
#pragma unroll
            for (int j = 0; j < 4; j++) {
                const int kg = kt + tx * 4 + j;
                const int dd = qg - kg;
                if (dd > WIN || dd < -WIN) s[i][j] = -1e30f;
                tmax = fmaxf(tmax, s[i][j]);
            }
#pragma unroll
            for (int ofs = 8; ofs > 0; ofs >>= 1)
                tmax = fmaxf(tmax, __shfl_xor_sync(0xffffffffu, tmax, ofs));
            const float mn = fmaxf(m[i], tmax);
            const float f  = expf(m[i] - mn);
            float sum = 0.f;
#pragma unroll
            for (int j = 0; j < 4; j++) {
                p[i][j] = expf(s[i][j] - mn);
                sum += p[i][j];
            }
#pragma unroll
            for (int ofs = 8; ofs > 0; ofs >>= 1)
                sum += __shfl_xor_sync(0xffffffffu, sum, ofs);
            l[i] = l[i] * f + sum;
            m[i] = mn;
#pragma unroll
            for (int j = 0; j < 4; j++) o[i][j] *= f;
        }
#pragma unroll
        for (int i = 0; i < 4; i++)
            *(float4*)(Ps + (ty * 4 + i) * 64 + tx * 4) =
                make_float4(p[i][0], p[i][1], p[i][2], p[i][3]);
        __syncthreads();

#pragma unroll 2
        for (int kk = 0; kk < 64; kk += 4) {
            float4 pv[4];
#pragma unroll
            for (int i = 0; i < 4; i++)
                pv[i] = *(const float4*)(Ps + (ty * 4 + i) * 64 + kk);
#pragma unroll
            for (int u = 0; u < 4; u++) {
                float vv[4];
                *(float4*)vv = *(const float4*)(Vs + (kk + u) * 64 + tx * 4);
#pragma unroll
                for (int i = 0; i < 4; i++) {
                    const float pu = (&pv[i].x)[u];
#pragma unroll
                    for (int j = 0; j < 4; j++)
                        o[i][j] = fmaf(pu, vv[j], o[i][j]);
                }
            }
        }
    }

#pragma unroll
    for (int i = 0; i < 4; i++) {
        const float inv = 1.0f / l[i];
        const float4 ov = make_float4(o[i][0] * inv, o[i][1] * inv,
                                      o[i][2] * inv, o[i][3] * inv);
        *(float4*)(out + (size_t)((size_t)b * Tn + qs + ty * 4 + i) * Dm
                       + h * HDm + tx * 4) = ov;
    }
}

// ---------------- launch ----------------
extern "C" void kernel_launch(void* const* d_in, const int* in_sizes, int n_in,
                              void* d_out, int out_size)
{
    const float* x    = (const float*)d_in[0];
    const float* in_w = (const float*)d_in[1];
    const float* in_b = (const float*)d_in[2];
    const float* ow   = (const float*)d_in[3];
    const float* ob   = (const float*)d_in[4];
    const float* w1   = (const float*)d_in[5];
    const float* b1   = (const float*)d_in[6];
    const float* w2   = (const float*)d_in[7];
    const float* b2   = (const float*)d_in[8];
    const float* ln1g = (const float*)d_in[9];
    const float* ln1b = (const float*)d_in[10];
    const float* ln2g = (const float*)d_in[11];
    const float* ln2b = (const float*)d_in[12];
    float* out = (float*)d_out;

    float *xn, *qkv, *attn, *x1, *hbuf;
    cudaGetSymbolAddress((void**)&xn,   g_xn);
    cudaGetSymbolAddress((void**)&qkv,  g_qkv);
    cudaGetSymbolAddress((void**)&attn, g_attn);
    cudaGetSymbolAddress((void**)&x1,   g_x1);
    cudaGetSymbolAddress((void**)&hbuf, g_h);

    const size_t attn_smem = (size_t)(2 * 64 * 68 + 2 * 64 * 64) * sizeof(float);
    cudaFuncSetAttribute(attn_kernel, cudaFuncAttributeMaxDynamicSharedMemorySize,
                         (int)attn_smem);

    // 1) LN1
    ln_kernel<<<NT, 256>>>(x, ln1g, ln1b, xn);
    // 2) QKV projection (tf32 TC)
    gemm_tf32_kernel<0, 0><<<dim3(3 * Dm / 128, NT / 128), 512>>>(
        xn, in_w, in_b, nullptr, qkv, NT, 3 * Dm, Dm);
    // 3) banded attention
    attn_kernel<<<dim3(Tn / 64, Hn, Bsz), 256, attn_smem>>>(qkv, attn);
    // 4) out projection + residual (tf32 TC)
    gemm_tf32_kernel<0, 1><<<dim3(Dm / 128, NT / 128), 512>>>(
        attn, ow, ob, x, x1, NT, Dm, Dm);
    // 5) LN2
    ln_kernel<<<NT, 256>>>(x1, ln2g, ln2b, xn);
    // 6) MLP up + exact GELU (tf32 TC)
    gemm_tf32_kernel<1, 0><<<dim3(MLPD / 128, NT / 128), 512>>>(
        xn, w1, b1, nullptr, hbuf, NT, MLPD, Dm);
    // 7) MLP down + residual -> d_out (tf32 TC)
    gemm_tf32_kernel<0, 1><<<dim3(Dm / 128, NT / 128), 512>>>(
        hbuf, w2, b2, x1, out, NT, Dm, MLPD);
}

// round 9
// speedup vs baseline: 2.7560x; 2.1409x over previous
#include <cuda_runtime.h>
#include <math.h>
#include <stdint.h>

#define Bsz  4
#define Tn   2048
#define Dm   768
#define Hn   12
#define HDm  64
#define MLPD 3072
#define WIN  256
#define NT   (Bsz * Tn)   /* 8192 rows */

// ---------------- static scratch ----------------
__device__ float g_xn  [NT * Dm];
__device__ float g_qkv [NT * 3 * Dm];
__device__ float g_attn[NT * Dm];
__device__ float g_x1  [NT * Dm];
__device__ float g_h   [NT * MLPD];

__device__ __forceinline__ uint32_t smem_u32(const void* p) {
    uint32_t a;
    asm("{ .reg .u64 t; cvta.to.shared.u64 t, %1; cvt.u32.u64 %0, t; }"
        : "=r"(a) : "l"(p));
    return a;
}

// ---------------- LayerNorm ----------------
__global__ void __launch_bounds__(256) ln_kernel(const float* __restrict__ x,
                                                 const float* __restrict__ g,
                                                 const float* __restrict__ b,
                                                 float* __restrict__ y)
{
    const int row = blockIdx.x;
    const float* xr = x + (size_t)row * Dm;
    float* yr = y + (size_t)row * Dm;
    const int t = threadIdx.x;

    float v[3];
    float s = 0.f, s2 = 0.f;
#pragma unroll
    for (int i = 0; i < 3; i++) {
        v[i] = xr[t + i * 256];
        s += v[i];
        s2 += v[i] * v[i];
    }
    __shared__ float red[16];
#pragma unroll
    for (int o = 16; o > 0; o >>= 1) {
        s  += __shfl_xor_sync(0xffffffffu, s,  o);
        s2 += __shfl_xor_sync(0xffffffffu, s2, o);
    }
    const int w = t >> 5;
    if ((t & 31) == 0) { red[w] = s; red[8 + w] = s2; }
    __syncthreads();
    s = 0.f; s2 = 0.f;
#pragma unroll
    for (int i = 0; i < 8; i++) { s += red[i]; s2 += red[8 + i]; }

    const float mean = s * (1.0f / Dm);
    float var = s2 * (1.0f / Dm) - mean * mean;
    var = fmaxf(var, 0.0f);
    const float rstd = rsqrtf(var + 1e-5f);
#pragma unroll
    for (int i = 0; i < 3; i++) {
        const int c = t + i * 256;
        yr[c] = (v[i] - mean) * rstd * g[c] + b[c];
    }
}

// ---------------- tf32 GEMM: cp.async + ldmatrix + mma.sync ----------------
// C[M,N] = A[M,K] @ B[N,K]^T + bias (+res) (+gelu)
// CTA tile 128x128, BK=32, 3-stage cp.async pipeline, 256 thr = 8 warps (2Mx4N),
// warp tile 64x32. Smem rows: 128B (32 fp32) XOR-swizzled in 16B chunks:
//   chunk(m, kq) at byte m*128 + ((kq ^ (m&7)) << 4).
// Raw fp32 fed to tf32 MMA (HW truncation).

#define BM 128
#define BN 128
#define BK 32
#define STAGES 3
#define ASTAGE (BM * BK * 4)               /* 16384 B per stage per matrix */
#define SMEM_GEMM (STAGES * 2 * ASTAGE)    /* 98304 B */

#define CPA16(dst, src) \
    asm volatile("cp.async.cg.shared.global [%0], [%1], 16;" \
                 :: "r"(dst), "l"(src) : "memory")
#define CPA_COMMIT() asm volatile("cp.async.commit_group;" ::: "memory")
#define CPA_WAIT1()  asm volatile("cp.async.wait_group 1;" ::: "memory")

#define LDSM4(r, addr)                                                        \
    asm volatile("ldmatrix.sync.aligned.m8n8.x4.shared.b16 {%0,%1,%2,%3}, [%4];" \
        : "=r"((r)[0]), "=r"((r)[1]), "=r"((r)[2]), "=r"((r)[3]) : "r"(addr))

#define MMA_TF32(c, A0, A1, A2, A3, B0, B1)                              \
    asm volatile(                                                        \
        "mma.sync.aligned.m16n8k8.row.col.f32.tf32.tf32.f32 "            \
        "{%0,%1,%2,%3}, {%4,%5,%6,%7}, {%8,%9}, {%0,%1,%2,%3};"          \
        : "+f"((c)[0]), "+f"((c)[1]), "+f"((c)[2]), "+f"((c)[3])         \
        : "r"(A0), "r"(A1), "r"(A2), "r"(A3), "r"(B0), "r"(B1))

template<int GELU, int RES>
__global__ void __launch_bounds__(256, 2) gemm_tc_kernel(
    const float* __restrict__ A,
    const float* __restrict__ B,
    const float* __restrict__ bias,
    const float* __restrict__ res,
    float* __restrict__ C,
    int M, int N, int K)
{
    extern __shared__ char sh[];
    const uint32_t sA = smem_u32(sh);
    const uint32_t sB = sA + STAGES * ASTAGE;

    const int t    = threadIdx.x;
    const int lane = t & 31;
    const int warp = t >> 5;
    const int wm   = warp & 1;    // 2 M-warps * 64
    const int wn   = warp >> 1;   // 4 N-warps * 32
    const int bm   = blockIdx.y * BM;
    const int bn   = blockIdx.x * BN;

    // cp.async mapping: thread t handles rows cm+32i (i=0..3), k-quad ckq
    const int cm  = t >> 3;
    const int ckq = t & 7;
    const uint32_t csw = (uint32_t)((ckq ^ (cm & 7)) << 4);
    const float* Ag = A + (size_t)(bm + cm) * K + ckq * 4;
    const float* Bg = B + (size_t)(bn + cm) * K + ckq * 4;
    const uint32_t daBase = cm * 128 + csw;

    // ldmatrix lane geometry
    const int lrow = ((lane >> 3) & 1) * 8 + (lane & 7);
    const int lk   = lane >> 4;    // 0/1 -> kq within k8
    const int l7   = lane & 7;
    uint32_t aoff[4], boff[2];
#pragma unroll
    for (int mt = 0; mt < 4; mt++) aoff[mt] = (uint32_t)((wm * 64 + mt * 16 + lrow) * 128);
#pragma unroll
    for (int n2 = 0; n2 < 2; n2++) boff[n2] = (uint32_t)((wn * 32 + n2 * 16 + lrow) * 128);

    float acc[4][4][4];
#pragma unroll
    for (int mt = 0; mt < 4; mt++)
#pragma unroll
        for (int nt = 0; nt < 4; nt++)
#pragma unroll
            for (int q = 0; q < 4; q++) acc[mt][nt][q] = 0.f;

    const int nch = K / BK;

    auto issue = [&](int ch, int s) {
        const float* ag = Ag + ch * BK;
        const float* bg = Bg + ch * BK;
        const uint32_t da = sA + s * ASTAGE + daBase;
        const uint32_t db = sB + s * ASTAGE + daBase;
#pragma unroll
        for (int i = 0; i < 4; i++) {
            CPA16(da + i * 32 * 128, ag + (size_t)i * 32 * K);
            CPA16(db + i * 32 * 128, bg + (size_t)i * 32 * K);
        }
    };

    issue(0, 0); CPA_COMMIT();
    issue(1, 1); CPA_COMMIT();

    for (int ch = 0; ch < nch; ch++) {
        CPA_WAIT1();
        __syncthreads();
        if (ch + 2 < nch) issue(ch + 2, (ch + 2) % STAGES);
        CPA_COMMIT();

        const uint32_t baA = sA + (ch % STAGES) * ASTAGE;
        const uint32_t baB = sB + (ch % STAGES) * ASTAGE;
#pragma unroll
        for (int ks = 0; ks < 4; ks++) {
            const uint32_t sw = (uint32_t)(((2 * ks + lk) ^ l7) << 4);
            uint32_t a[4][4], b[2][4];
#pragma unroll
            for (int mt = 0; mt < 4; mt++) LDSM4(a[mt], baA + aoff[mt] + sw);
#pragma unroll
            for (int n2 = 0; n2 < 2; n2++) LDSM4(b[n2], baB + boff[n2] + sw);
#pragma unroll
            for (int mt = 0; mt < 4; mt++)
#pragma unroll
                for (int nt = 0; nt < 4; nt++)
                    MMA_TF32(acc[mt][nt],
                             a[mt][0], a[mt][1], a[mt][2], a[mt][3],
                             b[nt >> 1][nt & 1], b[nt >> 1][2 + (nt & 1)]);
        }
    }

    // ---- epilogue ----
    const int g  = lane >> 2;
    const int l4 = lane & 3;
#pragma unroll
    for (int mt = 0; mt < 4; mt++) {
        const int r0 = bm + wm * 64 + mt * 16 + g;
#pragma unroll
        for (int nt = 0; nt < 4; nt++) {
            const int col = bn + wn * 32 + nt * 8 + l4 * 2;
            const float2 bia = *(const float2*)(bias + col);
            float v00 = acc[mt][nt][0] + bia.x, v01 = acc[mt][nt][1] + bia.y;
            float v10 = acc[mt][nt][2] + bia.x, v11 = acc[mt][nt][3] + bia.y;
            if (RES) {
                const float2 q0 = *(const float2*)(res + (size_t)r0 * N + col);
                const float2 q1 = *(const float2*)(res + (size_t)(r0 + 8) * N + col);
                v00 += q0.x; v01 += q0.y; v10 += q1.x; v11 += q1.y;
            }
            if (GELU) {
                v00 = 0.5f * v00 * (1.0f + erff(v00 * 0.70710678118654752f));
                v01 = 0.5f * v01 * (1.0f + erff(v01 * 0.70710678118654752f));
                v10 = 0.5f * v10 * (1.0f + erff(v10 * 0.70710678118654752f));
                v11 = 0.5f * v11 * (1.0f + erff(v11 * 0.70710678118654752f));
            }
            *(float2*)(C + (size_t)r0 * N + col)       = make_float2(v00, v01);
            *(float2*)(C + (size_t)(r0 + 8) * N + col) = make_float2(v10, v11);
        }
    }
}

// ---------------- banded flash attention (fp32) ----------------
__global__ void __launch_bounds__(256) attn_kernel(const float* __restrict__ qkv,
                                                   float* __restrict__ out)
{
    extern __shared__ float sm[];
    float* Qs = sm;                  // [64][68] transposed
    float* Ks = sm + 64 * 68;        // [64][68] transposed
    float* Vs = Ks + 64 * 68;        // [64][64]
    float* Ps = Vs + 64 * 64;        // [64][64]

    const int qs = blockIdx.x * 64;
    const int h  = blockIdx.y;
    const int b  = blockIdx.z;
    const int t  = threadIdx.x;
    const int tx = t & 15;
    const int ty = t >> 4;

    const size_t rstride = 3 * Dm;
    const float* base = qkv + (size_t)b * Tn * rstride + h * HDm;

#pragma unroll
    for (int i = 0; i < 4; i++) {
        const int lin = t + i * 256;
        const int r   = lin >> 4;
        const int c4  = (lin & 15) << 2;
        const float4 v = *(const float4*)(base + (size_t)(qs + r) * rstride + c4);
        Qs[(c4 + 0) * 68 + r] = v.x * 0.125f;
        Qs[(c4 + 1) * 68 + r] = v.y * 0.125f;
        Qs[(c4 + 2) * 68 + r] = v.z * 0.125f;
        Qs[(c4 + 3) * 68 + r] = v.w * 0.125f;
    }

    float m[4], l[4], o[4][4];
#pragma unroll
    for (int i = 0; i < 4; i++) {
        m[i] = -1e30f; l[i] = 0.f;
#pragma unroll
        for (int j = 0; j < 4; j++) o[i][j] = 0.f;
    }

    int kt0 = qs - WIN; if (kt0 < 0) kt0 = 0;
    int kt1 = qs + 64 + WIN; if (kt1 > Tn) kt1 = Tn;

    for (int kt = kt0; kt < kt1; kt += 64) {
        __syncthreads();
#pragma unroll
        for (int i = 0; i < 4; i++) {
            const int lin = t + i * 256;
            const int r   = lin >> 4;
            const int c4  = (lin & 15) << 2;
            const float* kr = base + (size_t)(kt + r) * rstride;
            const float4 kv = *(const float4*)(kr + Dm + c4);
            Ks[(c4 + 0) * 68 + r] = kv.x;
            Ks[(c4 + 1) * 68 + r] = kv.y;
            Ks[(c4 + 2) * 68 + r] = kv.z;
            Ks[(c4 + 3) * 68 + r] = kv.w;
            *(float4*)(Vs + r * 64 + c4) = *(const float4*)(kr + 2 * Dm + c4);
        }
        __syncthreads();

        float s[4][4];
#pragma unroll
        for (int i = 0; i < 4; i++)
#pragma unroll
            for (int j = 0; j < 4; j++) s[i][j] = 0.f;
#pragma unroll 8
        for (int kk = 0; kk < 64; kk++) {
            float aq[4], ak[4];
            *(float4*)aq = *(const float4*)(Qs + kk * 68 + ty * 4);
            *(float4*)ak = *(const float4*)(Ks + kk * 68 + tx * 4);
#pragma unroll
            for (int i = 0; i < 4; i++)
#pragma unroll
                for (int j = 0; j < 4; j++)
                    s[i][j] = fmaf(aq[i], ak[j], s[i][j]);
        }

        float p[4][4];
#pragma unroll
        for (int i = 0; i < 4; i++) {
            const int qg = qs + ty * 4 + i;
            float tmax = -1e30f;
#pragma unroll
            for (int j = 0; j < 4; j++) {
                const int kg = kt + tx * 4 + j;
                const int dd = qg - kg;
                if (dd > WIN || dd < -WIN) s[i][j] = -1e30f;
                tmax = fmaxf(tmax, s[i][j]);
            }
#pragma unroll
            for (int ofs = 8; ofs > 0; ofs >>= 1)
                tmax = fmaxf(tmax, __shfl_xor_sync(0xffffffffu, tmax, ofs));
            const float mn = fmaxf(m[i], tmax);
            const float f  = expf(m[i] - mn);
            float sum = 0.f;
#pragma unroll
            for (int j = 0; j < 4; j++) {
                p[i][j] = expf(s[i][j] - mn);
                sum += p[i][j];
            }
#pragma unroll
            for (int ofs = 8; ofs > 0; ofs >>= 1)
                sum += __shfl_xor_sync(0xffffffffu, sum, ofs);
            l[i] = l[i] * f + sum;
            m[i] = mn;
#pragma unroll
            for (int j = 0; j < 4; j++) o[i][j] *= f;
        }
#pragma unroll
        for (int i = 0; i < 4; i++)
            *(float4*)(Ps + (ty * 4 + i) * 64 + tx * 4) =
                make_float4(p[i][0], p[i][1], p[i][2], p[i][3]);
        __syncthreads();

#pragma unroll 2
        for (int kk = 0; kk < 64; kk += 4) {
            float4 pv[4];
#pragma unroll
            for (int i = 0; i < 4; i++)
                pv[i] = *(const float4*)(Ps + (ty * 4 + i) * 64 + kk);
#pragma unroll
            for (int u = 0; u < 4; u++) {
                float vv[4];
                *(float4*)vv = *(const float4*)(Vs + (kk + u) * 64 + tx * 4);
#pragma unroll
                for (int i = 0; i < 4; i++) {
                    const float pu = (&pv[i].x)[u];
#pragma unroll
                    for (int j = 0; j < 4; j++)
                        o[i][j] = fmaf(pu, vv[j], o[i][j]);
                }
            }
        }
    }

#pragma unroll
    for (int i = 0; i < 4; i++) {
        const float inv = 1.0f / l[i];
        const float4 ov = make_float4(o[i][0] * inv, o[i][1] * inv,
                                      o[i][2] * inv, o[i][3] * inv);
        *(float4*)(out + (size_t)((size_t)b * Tn + qs + ty * 4 + i) * Dm
                       + h * HDm + tx * 4) = ov;
    }
}

// ---------------- launch ----------------
extern "C" void kernel_launch(void* const* d_in, const int* in_sizes, int n_in,
                              void* d_out, int out_size)
{
    const float* x    = (const float*)d_in[0];
    const float* in_w = (const float*)d_in[1];
    const float* in_b = (const float*)d_in[2];
    const float* ow   = (const float*)d_in[3];
    const float* ob   = (const float*)d_in[4];
    const float* w1   = (const float*)d_in[5];
    const float* b1   = (const float*)d_in[6];
    const float* w2   = (const float*)d_in[7];
    const float* b2   = (const float*)d_in[8];
    const float* ln1g = (const float*)d_in[9];
    const float* ln1b = (const float*)d_in[10];
    const float* ln2g = (const float*)d_in[11];
    const float* ln2b = (const float*)d_in[12];
    float* out = (float*)d_out;

    float *xn, *qkv, *attn, *x1, *hbuf;
    cudaGetSymbolAddress((void**)&xn,   g_xn);
    cudaGetSymbolAddress((void**)&qkv,  g_qkv);
    cudaGetSymbolAddress((void**)&attn, g_attn);
    cudaGetSymbolAddress((void**)&x1,   g_x1);
    cudaGetSymbolAddress((void**)&hbuf, g_h);

    const size_t attn_smem = (size_t)(2 * 64 * 68 + 2 * 64 * 64) * sizeof(float);
    cudaFuncSetAttribute(attn_kernel, cudaFuncAttributeMaxDynamicSharedMemorySize,
                         (int)attn_smem);
    cudaFuncSetAttribute(gemm_tc_kernel<0, 0>, cudaFuncAttributeMaxDynamicSharedMemorySize, SMEM_GEMM);
    cudaFuncSetAttribute(gemm_tc_kernel<0, 1>, cudaFuncAttributeMaxDynamicSharedMemorySize, SMEM_GEMM);
    cudaFuncSetAttribute(gemm_tc_kernel<1, 0>, cudaFuncAttributeMaxDynamicSharedMemorySize, SMEM_GEMM);

    // 1) LN1
    ln_kernel<<<NT, 256>>>(x, ln1g, ln1b, xn);
    // 2) QKV projection
    gemm_tc_kernel<0, 0><<<dim3(3 * Dm / BN, NT / BM), 256, SMEM_GEMM>>>(
        xn, in_w, in_b, nullptr, qkv, NT, 3 * Dm, Dm);
    // 3) banded attention
    attn_kernel<<<dim3(Tn / 64, Hn, Bsz), 256, attn_smem>>>(qkv, attn);
    // 4) out projection + residual
    gemm_tc_kernel<0, 1><<<dim3(Dm / BN, NT / BM), 256, SMEM_GEMM>>>(
        attn, ow, ob, x, x1, NT, Dm, Dm);
    // 5) LN2
    ln_kernel<<<NT, 256>>>(x1, ln2g, ln2b, xn);
    // 6) MLP up + exact GELU
    gemm_tc_kernel<1, 0><<<dim3(MLPD / BN, NT / BM), 256, SMEM_GEMM>>>(
        xn, w1, b1, nullptr, hbuf, NT, MLPD, Dm);
    // 7) MLP down + residual -> d_out
    gemm_tc_kernel<0, 1><<<dim3(Dm / BN, NT / BM), 256, SMEM_GEMM>>>(
        hbuf, w2, b2, x1, out, NT, Dm, MLPD);
}

// round 10
// speedup vs baseline: 3.6353x; 1.3190x over previous
#include <cuda_runtime.h>
#include <math.h>
#include <stdint.h>

#define Bsz  4
#define Tn   2048
#define Dm   768
#define Hn   12
#define HDm  64
#define MLPD 3072
#define WIN  256
#define NT   (Bsz * Tn)   /* 8192 rows */

// ---------------- static scratch ----------------
__device__ float g_xn  [NT * Dm];
__device__ float g_qkv [NT * 3 * Dm];
__device__ float g_attn[NT * Dm];
__device__ float g_x1  [NT * Dm];
__device__ float g_h   [NT * MLPD];

__device__ __forceinline__ uint32_t smem_u32(const void* p) {
    uint32_t a;
    asm("{ .reg .u64 t; cvta.to.shared.u64 t, %1; cvt.u32.u64 %0, t; }"
        : "=r"(a) : "l"(p));
    return a;
}

#define CPA16(dst, src) \
    asm volatile("cp.async.cg.shared.global [%0], [%1], 16;" \
                 :: "r"(dst), "l"(src) : "memory")
#define CPA_COMMIT() asm volatile("cp.async.commit_group;" ::: "memory")
#define CPA_WAIT1()  asm volatile("cp.async.wait_group 1;" ::: "memory")
#define CPA_WAIT0()  asm volatile("cp.async.wait_group 0;" ::: "memory")

#define LDSM4(r, addr)                                                        \
    asm volatile("ldmatrix.sync.aligned.m8n8.x4.shared.b16 {%0,%1,%2,%3}, [%4];" \
        : "=r"((r)[0]), "=r"((r)[1]), "=r"((r)[2]), "=r"((r)[3]) : "r"(addr))

#define MMA_TF32(c, A0, A1, A2, A3, B0, B1)                              \
    asm volatile(                                                        \
        "mma.sync.aligned.m16n8k8.row.col.f32.tf32.tf32.f32 "            \
        "{%0,%1,%2,%3}, {%4,%5,%6,%7}, {%8,%9}, {%0,%1,%2,%3};"          \
        : "+f"((c)[0]), "+f"((c)[1]), "+f"((c)[2]), "+f"((c)[3])         \
        : "r"(A0), "r"(A1), "r"(A2), "r"(A3), "r"(B0), "r"(B1))

// ---------------- LayerNorm ----------------
__global__ void __launch_bounds__(256) ln_kernel(const float* __restrict__ x,
                                                 const float* __restrict__ g,
                                                 const float* __restrict__ b,
                                                 float* __restrict__ y)
{
    const int row = blockIdx.x;
    const float* xr = x + (size_t)row * Dm;
    float* yr = y + (size_t)row * Dm;
    const int t = threadIdx.x;

    float v[3];
    float s = 0.f, s2 = 0.f;
#pragma unroll
    for (int i = 0; i < 3; i++) {
        v[i] = xr[t + i * 256];
        s += v[i];
        s2 += v[i] * v[i];
    }
    __shared__ float red[16];
#pragma unroll
    for (int o = 16; o > 0; o >>= 1) {
        s  += __shfl_xor_sync(0xffffffffu, s,  o);
        s2 += __shfl_xor_sync(0xffffffffu, s2, o);
    }
    const int w = t >> 5;
    if ((t & 31) == 0) { red[w] = s; red[8 + w] = s2; }
    __syncthreads();
    s = 0.f; s2 = 0.f;
#pragma unroll
    for (int i = 0; i < 8; i++) { s += red[i]; s2 += red[8 + i]; }

    const float mean = s * (1.0f / Dm);
    float var = s2 * (1.0f / Dm) - mean * mean;
    var = fmaxf(var, 0.0f);
    const float rstd = rsqrtf(var + 1e-5f);
#pragma unroll
    for (int i = 0; i < 3; i++) {
        const int c = t + i * 256;
        yr[c] = (v[i] - mean) * rstd * g[c] + b[c];
    }
}

// ---------------- tf32 GEMM: cp.async + ldmatrix + mma.sync (unchanged R9) ----------------
#define BM 128
#define BN 128
#define BK 32
#define STAGES 3
#define ASTAGE (BM * BK * 4)
#define SMEM_GEMM (STAGES * 2 * ASTAGE)

template<int GELU, int RES>
__global__ void __launch_bounds__(256, 2) gemm_tc_kernel(
    const float* __restrict__ A,
    const float* __restrict__ B,
    const float* __restrict__ bias,
    const float* __restrict__ res,
    float* __restrict__ C,
    int M, int N, int K)
{
    extern __shared__ char sh[];
    const uint32_t sA = smem_u32(sh);
    const uint32_t sB = sA + STAGES * ASTAGE;

    const int t    = threadIdx.x;
    const int lane = t & 31;
    const int warp = t >> 5;
    const int wm   = warp & 1;
    const int wn   = warp >> 1;
    const int bm   = blockIdx.y * BM;
    const int bn   = blockIdx.x * BN;

    const int cm  = t >> 3;
    const int ckq = t & 7;
    const uint32_t csw = (uint32_t)((ckq ^ (cm & 7)) << 4);
    const float* Ag = A + (size_t)(bm + cm) * K + ckq * 4;
    const float* Bg = B + (size_t)(bn + cm) * K + ckq * 4;
    const uint32_t daBase = cm * 128 + csw;

    const int lrow = ((lane >> 3) & 1) * 8 + (lane & 7);
    const int lk   = lane >> 4;
    const int l7   = lane & 7;
    uint32_t aoff[4], boff[2];
#pragma unroll
    for (int mt = 0; mt < 4; mt++) aoff[mt] = (uint32_t)((wm * 64 + mt * 16 + lrow) * 128);
#pragma unroll
    for (int n2 = 0; n2 < 2; n2++) boff[n2] = (uint32_t)((wn * 32 + n2 * 16 + lrow) * 128);

    float acc[4][4][4];
#pragma unroll
    for (int mt = 0; mt < 4; mt++)
#pragma unroll
        for (int nt = 0; nt < 4; nt++)
#pragma unroll
            for (int q = 0; q < 4; q++) acc[mt][nt][q] = 0.f;

    const int nch = K / BK;

    auto issue = [&](int ch, int s) {
        const float* ag = Ag + ch * BK;
        const float* bg = Bg + ch * BK;
        const uint32_t da = sA + s * ASTAGE + daBase;
        const uint32_t db = sB + s * ASTAGE + daBase;
#pragma unroll
        for (int i = 0; i < 4; i++) {
            CPA16(da + i * 32 * 128, ag + (size_t)i * 32 * K);
            CPA16(db + i * 32 * 128, bg + (size_t)i * 32 * K);
        }
    };

    issue(0, 0); CPA_COMMIT();
    issue(1, 1); CPA_COMMIT();

    for (int ch = 0; ch < nch; ch++) {
        CPA_WAIT1();
        __syncthreads();
        if (ch + 2 < nch) issue(ch + 2, (ch + 2) % STAGES);
        CPA_COMMIT();

        const uint32_t baA = sA + (ch % STAGES) * ASTAGE;
        const uint32_t baB = sB + (ch % STAGES) * ASTAGE;
#pragma unroll
        for (int ks = 0; ks < 4; ks++) {
            const uint32_t sw = (uint32_t)(((2 * ks + lk) ^ l7) << 4);
            uint32_t a[4][4], b[2][4];
#pragma unroll
            for (int mt = 0; mt < 4; mt++) LDSM4(a[mt], baA + aoff[mt] + sw);
#pragma unroll
            for (int n2 = 0; n2 < 2; n2++) LDSM4(b[n2], baB + boff[n2] + sw);
#pragma unroll
            for (int mt = 0; mt < 4; mt++)
#pragma unroll
                for (int nt = 0; nt < 4; nt++)
                    MMA_TF32(acc[mt][nt],
                             a[mt][0], a[mt][1], a[mt][2], a[mt][3],
                             b[nt >> 1][nt & 1], b[nt >> 1][2 + (nt & 1)]);
        }
    }

    const int g  = lane >> 2;
    const int l4 = lane & 3;
#pragma unroll
    for (int mt = 0; mt < 4; mt++) {
        const int r0 = bm + wm * 64 + mt * 16 + g;
#pragma unroll
        for (int nt = 0; nt < 4; nt++) {
            const int col = bn + wn * 32 + nt * 8 + l4 * 2;
            const float2 bia = *(const float2*)(bias + col);
            float v00 = acc[mt][nt][0] + bia.x, v01 = acc[mt][nt][1] + bia.y;
            float v10 = acc[mt][nt][2] + bia.x, v11 = acc[mt][nt][3] + bia.y;
            if (RES) {
                const float2 q0 = *(const float2*)(res + (size_t)r0 * N + col);
                const float2 q1 = *(const float2*)(res + (size_t)(r0 + 8) * N + col);
                v00 += q0.x; v01 += q0.y; v10 += q1.x; v11 += q1.y;
            }
            if (GELU) {
                v00 = 0.5f * v00 * (1.0f + erff(v00 * 0.70710678118654752f));
                v01 = 0.5f * v01 * (1.0f + erff(v01 * 0.70710678118654752f));
                v10 = 0.5f * v10 * (1.0f + erff(v10 * 0.70710678118654752f));
                v11 = 0.5f * v11 * (1.0f + erff(v11 * 0.70710678118654752f));
            }
            *(float2*)(C + (size_t)r0 * N + col)       = make_float2(v00, v01);
            *(float2*)(C + (size_t)(r0 + 8) * N + col) = make_float2(v10, v11);
        }
    }
}

// ---------------- banded flash attention (tf32 tensor cores) ----------------
// Q tile 128 x 64 per CTA; KV tiles of 64 keys, double-buffered.
// Smem rows padded to 68 floats (272B): 16B-group index (17*row + chunk) % 8
// cycles all 8 groups -> conflict-free LDSM/STS without XOR swizzle.
// Layout (floats): Qs[128][68] | Ks[2][64][68] | Vt[2][64][68]  = 104448 B
#define AQ_F   0
#define AK_F   (128 * 68)
#define AV_F   (128 * 68 + 2 * 64 * 68)
#define SMEM_ATTN ((128 + 2 * 64 + 2 * 64) * 68 * 4)

__global__ void __launch_bounds__(256, 2) attn_kernel(const float* __restrict__ qkv,
                                                      float* __restrict__ out)
{
    extern __shared__ float smf[];
    const uint32_t sbase = smem_u32(smf);
    const uint32_t sQ = sbase;
    const uint32_t sK = sbase + AK_F * 4;
    const uint32_t sV = sbase + AV_F * 4;

    const int t    = threadIdx.x;
    const int lane = t & 31;
    const int w    = t >> 5;
    const int qs   = blockIdx.x * 128;
    const int h    = blockIdx.y;
    const int b    = blockIdx.z;
    const int bT   = b * Tn;
    const int h64  = h * HDm;

    const int lrow = ((lane >> 3) & 1) * 8 + (lane & 7);
    const int lk   = lane >> 4;
    const int g    = lane >> 2;
    const int l4   = lane & 3;

    const int kt0 = (qs - WIN > 0) ? qs - WIN : 0;
    const int kt1 = (qs + 128 + WIN < Tn) ? qs + 128 + WIN : Tn;
    const int n   = (kt1 - kt0) >> 6;

    // ---- loaders ----
    auto ldK = [&](int tile, int s) {
#pragma unroll
        for (int i = 0; i < 4; i++) {
            const int idx = t + i * 256;
            const int key = idx >> 4, c = idx & 15;
            CPA16(sK + s * (64 * 272) + key * 272 + c * 16,
                  qkv + (size_t)(bT + kt0 + tile * 64 + key) * 2304 + Dm + h64 + c * 4);
        }
    };
    auto ldV = [&](int tile, float* vr) {
#pragma unroll
        for (int q = 0; q < 4; q++) {
            const int kb = ((t >> 6) + q * 4) * 4;
            const float* src = qkv + (size_t)(bT + kt0 + tile * 64 + kb) * 2304
                                   + 2 * Dm + h64 + (t & 63);
#pragma unroll
            for (int i = 0; i < 4; i++) vr[q * 4 + i] = src[(size_t)i * 2304];
        }
    };
    auto stV = [&](int s, const float* vr) {
        const int dcol = t & 63;
#pragma unroll
        for (int q = 0; q < 4; q++) {
            const int kb = ((t >> 6) + q * 4) * 4;
            *(float4*)(smf + AV_F + s * (64 * 68) + dcol * 68 + kb) =
                make_float4(vr[q * 4], vr[q * 4 + 1], vr[q * 4 + 2], vr[q * 4 + 3]);
        }
    };

    // ---- prologue: Q + first tiles ----
#pragma unroll
    for (int i = 0; i < 8; i++) {
        const int idx = t + i * 256;
        const int r = idx >> 4, c = idx & 15;
        CPA16(sQ + r * 272 + c * 16,
              qkv + (size_t)(bT + qs + r) * 2304 + h64 + c * 4);
    }
    ldK(0, 0);
    CPA_COMMIT();
    float vr[16];
    ldV(0, vr);
    CPA_WAIT0();
    __syncthreads();
    stV(0, vr);
    if (n > 1) { ldV(1, vr); ldK(1, 1); }
    CPA_COMMIT();
    __syncthreads();

    // ---- state ----
    float o[8][4];
#pragma unroll
    for (int j = 0; j < 8; j++)
#pragma unroll
        for (int q = 0; q < 4; q++) o[j][q] = 0.f;
    float m0 = -1e30f, m1 = -1e30f, l0 = 0.f, l1 = 0.f;

    const int qmin = qs + w * 16;
    const int q0 = qmin + g, q1 = q0 + 8;
    const uint32_t qb = sQ + (w * 16 + lrow) * 272;
    const int srcA = l4 >> 1, srcB = srcA + 2;
    const bool hi = (l4 & 1) != 0;

    for (int it = 0; it < n; it++) {
        const int s  = it & 1;
        const int kt = kt0 + it * 64;
        const uint32_t kb_ = sK + s * (64 * 272) + lrow * 272;
        const uint32_t vb_ = sV + s * (64 * 272) + lrow * 272;

        // ---- S = Q @ K^T ----
        float sc[8][4];
#pragma unroll
        for (int j = 0; j < 8; j++)
#pragma unroll
            for (int q = 0; q < 4; q++) sc[j][q] = 0.f;
#pragma unroll
        for (int ks = 0; ks < 8; ks++) {
            const uint32_t ck = (uint32_t)((2 * ks + lk) << 4);
            uint32_t qa[4];
            LDSM4(qa, qb + ck);
#pragma unroll
            for (int q4 = 0; q4 < 4; q4++) {
                uint32_t kb4[4];
                LDSM4(kb4, kb_ + q4 * (16 * 272) + ck);
                MMA_TF32(sc[2 * q4],     qa[0], qa[1], qa[2], qa[3], kb4[0], kb4[2]);
                MMA_TF32(sc[2 * q4 + 1], qa[0], qa[1], qa[2], qa[3], kb4[1], kb4[3]);
            }
        }

        // ---- scale + band mask + online softmax ----
        const bool full = (kt >= qmin + 15 - WIN) && (kt + 63 <= qmin + WIN);
        float tm0 = -2e30f, tm1 = -2e30f;
#pragma unroll
        for (int j = 0; j < 8; j++) {
#pragma unroll
            for (int q = 0; q < 4; q++) sc[j][q] *= 0.125f;
            if (!full) {
                const int kc = kt + 8 * j + 2 * l4;
                if (q0 - kc > WIN || kc - q0 > WIN)         sc[j][0] = -2e30f;
                if (q0 - kc - 1 > WIN || kc + 1 - q0 > WIN) sc[j][1] = -2e30f;
                if (q1 - kc > WIN || kc - q1 > WIN)         sc[j][2] = -2e30f;
                if (q1 - kc - 1 > WIN || kc + 1 - q1 > WIN) sc[j][3] = -2e30f;
            }
            tm0 = fmaxf(tm0, fmaxf(sc[j][0], sc[j][1]));
            tm1 = fmaxf(tm1, fmaxf(sc[j][2], sc[j][3]));
        }
        tm0 = fmaxf(tm0, __shfl_xor_sync(0xffffffffu, tm0, 1));
        tm0 = fmaxf(tm0, __shfl_xor_sync(0xffffffffu, tm0, 2));
        tm1 = fmaxf(tm1, __shfl_xor_sync(0xffffffffu, tm1, 1));
        tm1 = fmaxf(tm1, __shfl_xor_sync(0xffffffffu, tm1, 2));

        const float m0n = fmaxf(m0, tm0), m1n = fmaxf(m1, tm1);
        const float f0 = expf(m0 - m0n), f1 = expf(m1 - m1n);
        float s0 = 0.f, s1 = 0.f;
#pragma unroll
        for (int j = 0; j < 8; j++) {
            sc[j][0] = expf(sc[j][0] - m0n);
            sc[j][1] = expf(sc[j][1] - m0n);
            sc[j][2] = expf(sc[j][2] - m1n);
            sc[j][3] = expf(sc[j][3] - m1n);
            s0 += sc[j][0] + sc[j][1];
            s1 += sc[j][2] + sc[j][3];
        }
        s0 += __shfl_xor_sync(0xffffffffu, s0, 1);
        s0 += __shfl_xor_sync(0xffffffffu, s0, 2);
        s1 += __shfl_xor_sync(0xffffffffu, s1, 1);
        s1 += __shfl_xor_sync(0xffffffffu, s1, 2);
        l0 = l0 * f0 + s0;
        l1 = l1 * f1 + s1;
        m0 = m0n; m1 = m1n;
#pragma unroll
        for (int j = 0; j < 8; j++) {
            o[j][0] *= f0; o[j][1] *= f0; o[j][2] *= f1; o[j][3] *= f1;
        }

        // ---- O += P @ V (P fragments via quad shfl permute) ----
#pragma unroll
        for (int ks = 0; ks < 8; ks++) {
            const float x0 = __shfl_sync(0xffffffffu, sc[ks][0], srcA, 4);
            const float x1 = __shfl_sync(0xffffffffu, sc[ks][1], srcA, 4);
            const float y0 = __shfl_sync(0xffffffffu, sc[ks][0], srcB, 4);
            const float y1 = __shfl_sync(0xffffffffu, sc[ks][1], srcB, 4);
            const float z0 = __shfl_sync(0xffffffffu, sc[ks][2], srcA, 4);
            const float z1 = __shfl_sync(0xffffffffu, sc[ks][3], srcA, 4);
            const float u0 = __shfl_sync(0xffffffffu, sc[ks][2], srcB, 4);
            const float u1 = __shfl_sync(0xffffffffu, sc[ks][3], srcB, 4);
            const uint32_t a0 = __float_as_uint(hi ? x1 : x0);
            const uint32_t a1 = __float_as_uint(hi ? z1 : z0);
            const uint32_t a2 = __float_as_uint(hi ? y1 : y0);
            const uint32_t a3 = __float_as_uint(hi ? u1 : u0);
            const uint32_t ck = (uint32_t)((2 * ks + lk) << 4);
#pragma unroll
            for (int q4 = 0; q4 < 4; q4++) {
                uint32_t vb4[4];
                LDSM4(vb4, vb_ + q4 * (16 * 272) + ck);
                MMA_TF32(o[2 * q4],     a0, a1, a2, a3, vb4[0], vb4[2]);
                MMA_TF32(o[2 * q4 + 1], a0, a1, a2, a3, vb4[1], vb4[3]);
            }
        }

        // ---- advance pipeline ----
        if (it + 1 < n) {
            CPA_WAIT0();
            __syncthreads();
            stV(s ^ 1, vr);
            if (it + 2 < n) { ldV(it + 2, vr); ldK(it + 2, s); }
            CPA_COMMIT();
            __syncthreads();
        }
    }

    // ---- write output ----
    const float i0 = 1.0f / l0, i1 = 1.0f / l1;
    float* o0 = out + (size_t)(bT + qs + w * 16 + g) * Dm + h64;
    float* o1 = o0 + (size_t)8 * Dm;
#pragma unroll
    for (int j = 0; j < 8; j++) {
        const int col = 8 * j + 2 * l4;
        *(float2*)(o0 + col) = make_float2(o[j][0] * i0, o[j][1] * i0);
        *(float2*)(o1 + col) = make_float2(o[j][2] * i1, o[j][3] * i1);
    }
}

// ---------------- launch ----------------
extern "C" void kernel_launch(void* const* d_in, const int* in_sizes, int n_in,
                              void* d_out, int out_size)
{
    const float* x    = (const float*)d_in[0];
    const float* in_w = (const float*)d_in[1];
    const float* in_b = (const float*)d_in[2];
    const float* ow   = (const float*)d_in[3];
    const float* ob   = (const float*)d_in[4];
    const float* w1   = (const float*)d_in[5];
    const float* b1   = (const float*)d_in[6];
    const float* w2   = (const float*)d_in[7];
    const float* b2   = (const float*)d_in[8];
    const float* ln1g = (const float*)d_in[9];
    const float* ln1b = (const float*)d_in[10];
    const float* ln2g = (const float*)d_in[11];
    const float* ln2b = (const float*)d_in[12];
    float* out = (float*)d_out;

    float *xn, *qkv, *attn, *x1, *hbuf;
    cudaGetSymbolAddress((void**)&xn,   g_xn);
    cudaGetSymbolAddress((void**)&qkv,  g_qkv);
    cudaGetSymbolAddress((void**)&attn, g_attn);
    cudaGetSymbolAddress((void**)&x1,   g_x1);
    cudaGetSymbolAddress((void**)&hbuf, g_h);

    cudaFuncSetAttribute(attn_kernel, cudaFuncAttributeMaxDynamicSharedMemorySize, SMEM_ATTN);
    cudaFuncSetAttribute(gemm_tc_kernel<0, 0>, cudaFuncAttributeMaxDynamicSharedMemorySize, SMEM_GEMM);
    cudaFuncSetAttribute(gemm_tc_kernel<0, 1>, cudaFuncAttributeMaxDynamicSharedMemorySize, SMEM_GEMM);
    cudaFuncSetAttribute(gemm_tc_kernel<1, 0>, cudaFuncAttributeMaxDynamicSharedMemorySize, SMEM_GEMM);

    // 1) LN1
    ln_kernel<<<NT, 256>>>(x, ln1g, ln1b, xn);
    // 2) QKV projection
    gemm_tc_kernel<0, 0><<<dim3(3 * Dm / BN, NT / BM), 256, SMEM_GEMM>>>(
        xn, in_w, in_b, nullptr, qkv, NT, 3 * Dm, Dm);
    // 3) banded attention (tensor cores)
    attn_kernel<<<dim3(Tn / 128, Hn, Bsz), 256, SMEM_ATTN>>>(qkv, attn);
    // 4) out projection + residual
    gemm_tc_kernel<0, 1><<<dim3(Dm / BN, NT / BM), 256, SMEM_GEMM>>>(
        attn, ow, ob, x, x1, NT, Dm, Dm);
    // 5) LN2
    ln_kernel<<<NT, 256>>>(x1, ln2g, ln2b, xn);
    // 6) MLP up + exact GELU
    gemm_tc_kernel<1, 0><<<dim3(MLPD / BN, NT / BM), 256, SMEM_GEMM>>>(
        xn, w1, b1, nullptr, hbuf, NT, MLPD, Dm);
    // 7) MLP down + residual -> d_out
    gemm_tc_kernel<0, 1><<<dim3(Dm / BN, NT / BM), 256, SMEM_GEMM>>>(
        hbuf, w2, b2, x1, out, NT, Dm, MLPD);
}

// round 11
// speedup vs baseline: 6.2039x; 1.7066x over previous
#include <cuda_runtime.h>
#include <cuda_fp16.h>
#include <math.h>
#include <stdint.h>

#define Bsz  4
#define Tn   2048
#define Dm   768
#define Hn   12
#define HDm  64
#define MLPD 3072
#define WIN  256
#define NT   (Bsz * Tn)   /* 8192 rows */

// ---------------- static scratch ----------------
__device__ __half g_xnh  [NT * Dm];
__device__ __half g_qkvh [NT * 3 * Dm];
__device__ __half g_attnh[NT * Dm];
__device__ __half g_hh   [NT * MLPD];
__device__ float  g_x1   [NT * Dm];
__device__ __half g_wqkvh[3 * Dm * Dm];
__device__ __half g_owh  [Dm * Dm];
__device__ __half g_w1h  [MLPD * Dm];
__device__ __half g_w2h  [Dm * MLPD];

__device__ __forceinline__ uint32_t smem_u32(const void* p) {
    uint32_t a;
    asm("{ .reg .u64 t; cvta.to.shared.u64 t, %1; cvt.u32.u64 %0, t; }"
        : "=r"(a) : "l"(p));
    return a;
}

#define CPA16(dst, src) \
    asm volatile("cp.async.cg.shared.global [%0], [%1], 16;" \
                 :: "r"(dst), "l"(src) : "memory")
#define CPA_COMMIT() asm volatile("cp.async.commit_group;" ::: "memory")
#define CPA_WAIT1()  asm volatile("cp.async.wait_group 1;" ::: "memory")
#define CPA_WAIT0()  asm volatile("cp.async.wait_group 0;" ::: "memory")

#define LDSM4(r, addr)                                                        \
    asm volatile("ldmatrix.sync.aligned.m8n8.x4.shared.b16 {%0,%1,%2,%3}, [%4];" \
        : "=r"((r)[0]), "=r"((r)[1]), "=r"((r)[2]), "=r"((r)[3]) : "r"(addr))
#define LDSM4T(r, addr)                                                       \
    asm volatile("ldmatrix.sync.aligned.m8n8.x4.trans.shared.b16 {%0,%1,%2,%3}, [%4];" \
        : "=r"((r)[0]), "=r"((r)[1]), "=r"((r)[2]), "=r"((r)[3]) : "r"(addr))

#define MMA_F16(c, A0, A1, A2, A3, B0, B1)                               \
    asm volatile(                                                        \
        "mma.sync.aligned.m16n8k16.row.col.f32.f16.f16.f32 "             \
        "{%0,%1,%2,%3}, {%4,%5,%6,%7}, {%8,%9}, {%0,%1,%2,%3};"          \
        : "+f"((c)[0]), "+f"((c)[1]), "+f"((c)[2]), "+f"((c)[3])         \
        : "r"(A0), "r"(A1), "r"(A2), "r"(A3), "r"(B0), "r"(B1))

__device__ __forceinline__ uint32_t packh2(float a, float b) {
    __half2 h = __floats2half2_rn(a, b);
    return *(uint32_t*)&h;
}

// ---------------- fp32 -> fp16 conversion ----------------
__global__ void __launch_bounds__(256) f2h_kernel(const float* __restrict__ s,
                                                  __half* __restrict__ d, int n)
{
    const int i = (blockIdx.x * 256 + threadIdx.x) * 4;
    if (i < n) {
        const float4 v = *(const float4*)(s + i);
        *(__half2*)(d + i)     = __floats2half2_rn(v.x, v.y);
        *(__half2*)(d + i + 2) = __floats2half2_rn(v.z, v.w);
    }
}

// ---------------- LayerNorm (fp32 in -> fp16 out) ----------------
__global__ void __launch_bounds__(256) ln_kernel(const float* __restrict__ x,
                                                 const float* __restrict__ g,
                                                 const float* __restrict__ b,
                                                 __half* __restrict__ y)
{
    const int row = blockIdx.x;
    const float* xr = x + (size_t)row * Dm;
    __half* yr = y + (size_t)row * Dm;
    const int t = threadIdx.x;

    float v[3];
    float s = 0.f, s2 = 0.f;
#pragma unroll
    for (int i = 0; i < 3; i++) {
        v[i] = xr[t + i * 256];
        s += v[i];
        s2 += v[i] * v[i];
    }
    __shared__ float red[16];
#pragma unroll
    for (int o = 16; o > 0; o >>= 1) {
        s  += __shfl_xor_sync(0xffffffffu, s,  o);
        s2 += __shfl_xor_sync(0xffffffffu, s2, o);
    }
    const int w = t >> 5;
    if ((t & 31) == 0) { red[w] = s; red[8 + w] = s2; }
    __syncthreads();
    s = 0.f; s2 = 0.f;
#pragma unroll
    for (int i = 0; i < 8; i++) { s += red[i]; s2 += red[8 + i]; }

    const float mean = s * (1.0f / Dm);
    float var = s2 * (1.0f / Dm) - mean * mean;
    var = fmaxf(var, 0.0f);
    const float rstd = rsqrtf(var + 1e-5f);
#pragma unroll
    for (int i = 0; i < 3; i++) {
        const int c = t + i * 256;
        yr[c] = __float2half_rn((v[i] - mean) * rstd * g[c] + b[c]);
    }
}

// ---------------- fp16 GEMM: cp.async + ldmatrix + mma.m16n8k16 ----------------
// C[M,N] = A[M,K] @ B[N,K]^T + bias (+res) (+gelu). A,B fp16; accum fp32.
// CTA 128x128, BK=64 halves (128B rows), 3-stage cp.async, 8 warps (2Mx4N),
// warp tile 64x32. 16B chunks XOR-swizzled: chunk ^= (row & 7).
#define BM 128
#define BN 128
#define BKH 64
#define STAGES 3
#define ASTAGE (BM * BKH * 2)             /* 16384 B */
#define SMEM_GEMM (STAGES * 2 * ASTAGE)   /* 98304 B */

template<int GELU, int RES, int OUTH>
__global__ void __launch_bounds__(256, 2) gemm_h_kernel(
    const __half* __restrict__ A,
    const __half* __restrict__ B,
    const float* __restrict__ bias,
    const float* __restrict__ res,
    void* __restrict__ Cv,
    int M, int N, int K)
{
    extern __shared__ char sh[];
    const uint32_t sA = smem_u32(sh);
    const uint32_t sB = sA + STAGES * ASTAGE;

    const int t    = threadIdx.x;
    const int lane = t & 31;
    const int warp = t >> 5;
    const int wm   = warp & 1;
    const int wn   = warp >> 1;
    const int bm   = blockIdx.y * BM;
    const int bn   = blockIdx.x * BN;

    // cp.async mapping: thread t -> rows cm+32i, 16B chunk ckq
    const int cm  = t >> 3;
    const int ckq = t & 7;
    const uint32_t daBase = cm * 128 + (uint32_t)((ckq ^ (cm & 7)) << 4);
    const __half* Ag = A + (size_t)(bm + cm) * K + ckq * 8;
    const __half* Bg = B + (size_t)(bn + cm) * K + ckq * 8;

    const int l15 = lane & 15;
    const int lk  = lane >> 4;
    const int l7  = lane & 7;
    uint32_t aoff[4], boff[2];
#pragma unroll
    for (int mt = 0; mt < 4; mt++) aoff[mt] = (uint32_t)((wm * 64 + mt * 16 + l15) * 128);
#pragma unroll
    for (int n2 = 0; n2 < 2; n2++) boff[n2] = (uint32_t)((wn * 32 + n2 * 16 + l15) * 128);

    float acc[4][4][4];
#pragma unroll
    for (int mt = 0; mt < 4; mt++)
#pragma unroll
        for (int nt = 0; nt < 4; nt++)
#pragma unroll
            for (int q = 0; q < 4; q++) acc[mt][nt][q] = 0.f;

    const int nch = K / BKH;

    auto issue = [&](int ch, int s) {
        const __half* ag = Ag + ch * BKH;
        const __half* bg = Bg + ch * BKH;
        const uint32_t da = sA + s * ASTAGE + daBase;
        const uint32_t db = sB + s * ASTAGE + daBase;
#pragma unroll
        for (int i = 0; i < 4; i++) {
            CPA16(da + i * 32 * 128, ag + (size_t)i * 32 * K);
            CPA16(db + i * 32 * 128, bg + (size_t)i * 32 * K);
        }
    };

    issue(0, 0); CPA_COMMIT();
    issue(1, 1); CPA_COMMIT();

    for (int ch = 0; ch < nch; ch++) {
        CPA_WAIT1();
        __syncthreads();
        if (ch + 2 < nch) issue(ch + 2, (ch + 2) % STAGES);
        CPA_COMMIT();

        const uint32_t baA = sA + (ch % STAGES) * ASTAGE;
        const uint32_t baB = sB + (ch % STAGES) * ASTAGE;
#pragma unroll
        for (int ks = 0; ks < 4; ks++) {
            const uint32_t sw = (uint32_t)(((2 * ks + lk) ^ l7) << 4);
            uint32_t a[4][4], b[2][4];
#pragma unroll
            for (int mt = 0; mt < 4; mt++) LDSM4(a[mt], baA + aoff[mt] + sw);
#pragma unroll
            for (int n2 = 0; n2 < 2; n2++) LDSM4(b[n2], baB + boff[n2] + sw);
#pragma unroll
            for (int mt = 0; mt < 4; mt++)
#pragma unroll
                for (int nt = 0; nt < 4; nt++)
                    MMA_F16(acc[mt][nt],
                            a[mt][0], a[mt][1], a[mt][2], a[mt][3],
                            b[nt >> 1][nt & 1], b[nt >> 1][2 + (nt & 1)]);
        }
    }

    // ---- epilogue ----
    const int g  = lane >> 2;
    const int l4 = lane & 3;
#pragma unroll
    for (int mt = 0; mt < 4; mt++) {
        const int r0 = bm + wm * 64 + mt * 16 + g;
#pragma unroll
        for (int nt = 0; nt < 4; nt++) {
            const int col = bn + wn * 32 + nt * 8 + l4 * 2;
            const float2 bia = *(const float2*)(bias + col);
            float v00 = acc[mt][nt][0] + bia.x, v01 = acc[mt][nt][1] + bia.y;
            float v10 = acc[mt][nt][2] + bia.x, v11 = acc[mt][nt][3] + bia.y;
            if (RES) {
                const float2 q0 = *(const float2*)(res + (size_t)r0 * N + col);
                const float2 q1 = *(const float2*)(res + (size_t)(r0 + 8) * N + col);
                v00 += q0.x; v01 += q0.y; v10 += q1.x; v11 += q1.y;
            }
            if (GELU) {
                v00 = 0.5f * v00 * (1.0f + erff(v00 * 0.70710678118654752f));
                v01 = 0.5f * v01 * (1.0f + erff(v01 * 0.70710678118654752f));
                v10 = 0.5f * v10 * (1.0f + erff(v10 * 0.70710678118654752f));
                v11 = 0.5f * v11 * (1.0f + erff(v11 * 0.70710678118654752f));
            }
            if (OUTH) {
                __half* Ch = (__half*)Cv;
                *(__half2*)(Ch + (size_t)r0 * N + col)       = __floats2half2_rn(v00, v01);
                *(__half2*)(Ch + (size_t)(r0 + 8) * N + col) = __floats2half2_rn(v10, v11);
            } else {
                float* Cf = (float*)Cv;
                *(float2*)(Cf + (size_t)r0 * N + col)       = make_float2(v00, v01);
                *(float2*)(Cf + (size_t)(r0 + 8) * N + col) = make_float2(v10, v11);
            }
        }
    }
}

// ---------------- banded flash attention (fp16 mma) ----------------
// Q tile 128x64h per CTA, KV tiles 64 keys double-buffered, 8 warps.
// Smem rows 128B, 16B chunks swizzled: chunk ^= (row&7).
// Q: 16KB | K: 2x8KB | V: 2x8KB = 48KB.
#define SATT_Q 0
#define SATT_K 16384
#define SATT_V 32768
#define SMEM_ATTN 49152

__global__ void __launch_bounds__(256, 2) attn_kernel(const __half* __restrict__ qkv,
                                                      __half* __restrict__ out)
{
    extern __shared__ char shm[];
    const uint32_t sbase = smem_u32(shm);
    const uint32_t sQ = sbase + SATT_Q;
    const uint32_t sK = sbase + SATT_K;
    const uint32_t sV = sbase + SATT_V;

    const int t    = threadIdx.x;
    const int lane = t & 31;
    const int w    = t >> 5;
    const int qs   = blockIdx.x * 128;
    const int h    = blockIdx.y;
    const int b    = blockIdx.z;
    const int bT   = b * Tn;
    const int h64  = h * HDm;

    const int l15 = lane & 15;
    const int lk  = lane >> 4;
    const int l7  = lane & 7;
    const int g   = lane >> 2;
    const int l4  = lane & 3;
    const int trow = ((lane >> 3) & 1) * 8 + (lane & 7);  // for trans V loads

    const int kt0 = (qs - WIN > 0) ? qs - WIN : 0;
    const int kt1 = (qs + 128 + WIN < Tn) ? qs + 128 + WIN : Tn;
    const int n   = (kt1 - kt0) >> 6;

    auto ldQ = [&]() {
#pragma unroll
        for (int i = 0; i < 4; i++) {
            const int idx = t + i * 256;
            const int r = idx >> 3, c = idx & 7;
            CPA16(sQ + r * 128 + ((c ^ (r & 7)) << 4),
                  qkv + (size_t)(bT + qs + r) * 2304 + h64 + c * 8);
        }
    };
    auto ldKV = [&](int tile, int s) {
#pragma unroll
        for (int i = 0; i < 2; i++) {
            const int idx = t + i * 256;
            const int key = idx >> 3, c = idx & 7;
            const uint32_t off = s * 8192 + key * 128 + ((c ^ (key & 7)) << 4);
            const __half* src = qkv + (size_t)(bT + kt0 + tile * 64 + key) * 2304 + h64 + c * 8;
            CPA16(sK + off, src + Dm);
            CPA16(sV + off, src + 2 * Dm);
        }
    };

    ldQ(); ldKV(0, 0); CPA_COMMIT();
    if (n > 1) ldKV(1, 1);
    CPA_COMMIT();

    float o[8][4];
#pragma unroll
    for (int j = 0; j < 8; j++)
#pragma unroll
        for (int q = 0; q < 4; q++) o[j][q] = 0.f;
    float m0 = -1e30f, m1 = -1e30f, l0 = 0.f, l1 = 0.f;

    const int qmin = qs + w * 16;
    const int q0 = qmin + g, q1 = q0 + 8;
    const uint32_t qb = sQ + (w * 16 + l15) * 128;

    for (int it = 0; it < n; it++) {
        const int s  = it & 1;
        const int kt = kt0 + it * 64;

        if (it + 1 < n) CPA_WAIT1(); else CPA_WAIT0();
        __syncthreads();

        // ---- S = Q @ K^T (4 k16 steps over head dim) ----
        float sc[8][4];
#pragma unroll
        for (int j = 0; j < 8; j++)
#pragma unroll
            for (int q = 0; q < 4; q++) sc[j][q] = 0.f;

        const uint32_t kb_ = sK + s * 8192;
#pragma unroll
        for (int ks = 0; ks < 4; ks++) {
            const uint32_t sw = (uint32_t)(((2 * ks + lk) ^ l7) << 4);
            uint32_t qa[4];
            LDSM4(qa, qb + sw);
#pragma unroll
            for (int j2 = 0; j2 < 4; j2++) {
                uint32_t kb4[4];
                LDSM4(kb4, kb_ + (j2 * 16 + l15) * 128 + sw);
                MMA_F16(sc[2 * j2],     qa[0], qa[1], qa[2], qa[3], kb4[0], kb4[2]);
                MMA_F16(sc[2 * j2 + 1], qa[0], qa[1], qa[2], qa[3], kb4[1], kb4[3]);
            }
        }

        // ---- scale + band mask + online softmax ----
        const bool full = (kt >= qmin + 15 - WIN) && (kt + 63 <= qmin + WIN);
        float tm0 = -2e30f, tm1 = -2e30f;
#pragma unroll
        for (int j = 0; j < 8; j++) {
#pragma unroll
            for (int q = 0; q < 4; q++) sc[j][q] *= 0.125f;
            if (!full) {
                const int kc = kt + 8 * j + 2 * l4;
                if (q0 - kc > WIN || kc - q0 > WIN)         sc[j][0] = -2e30f;
                if (q0 - kc - 1 > WIN || kc + 1 - q0 > WIN) sc[j][1] = -2e30f;
                if (q1 - kc > WIN || kc - q1 > WIN)         sc[j][2] = -2e30f;
                if (q1 - kc - 1 > WIN || kc + 1 - q1 > WIN) sc[j][3] = -2e30f;
            }
            tm0 = fmaxf(tm0, fmaxf(sc[j][0], sc[j][1]));
            tm1 = fmaxf(tm1, fmaxf(sc[j][2], sc[j][3]));
        }
        tm0 = fmaxf(tm0, __shfl_xor_sync(0xffffffffu, tm0, 1));
        tm0 = fmaxf(tm0, __shfl_xor_sync(0xffffffffu, tm0, 2));
        tm1 = fmaxf(tm1, __shfl_xor_sync(0xffffffffu, tm1, 1));
        tm1 = fmaxf(tm1, __shfl_xor_sync(0xffffffffu, tm1, 2));

        const float m0n = fmaxf(m0, tm0), m1n = fmaxf(m1, tm1);
        const float f0 = expf(m0 - m0n), f1 = expf(m1 - m1n);
        float s0 = 0.f, s1 = 0.f;
#pragma unroll
        for (int j = 0; j < 8; j++) {
            sc[j][0] = expf(sc[j][0] - m0n);
            sc[j][1] = expf(sc[j][1] - m0n);
            sc[j][2] = expf(sc[j][2] - m1n);
            sc[j][3] = expf(sc[j][3] - m1n);
            s0 += sc[j][0] + sc[j][1];
            s1 += sc[j][2] + sc[j][3];
        }
        s0 += __shfl_xor_sync(0xffffffffu, s0, 1);
        s0 += __shfl_xor_sync(0xffffffffu, s0, 2);
        s1 += __shfl_xor_sync(0xffffffffu, s1, 1);
        s1 += __shfl_xor_sync(0xffffffffu, s1, 2);
        l0 = l0 * f0 + s0;
        l1 = l1 * f1 + s1;
        m0 = m0n; m1 = m1n;
#pragma unroll
        for (int j = 0; j < 8; j++) {
            o[j][0] *= f0; o[j][1] *= f0; o[j][2] *= f1; o[j][3] *= f1;
        }

        // ---- O += P @ V ; P fragments direct from accumulator layout ----
        const uint32_t vb_ = sV + s * 8192;
#pragma unroll
        for (int j2 = 0; j2 < 4; j2++) {
            const uint32_t a0 = packh2(sc[2 * j2][0],     sc[2 * j2][1]);
            const uint32_t a1 = packh2(sc[2 * j2][2],     sc[2 * j2][3]);
            const uint32_t a2 = packh2(sc[2 * j2 + 1][0], sc[2 * j2 + 1][1]);
            const uint32_t a3 = packh2(sc[2 * j2 + 1][2], sc[2 * j2 + 1][3]);
            const uint32_t vrow = vb_ + (j2 * 16 + trow) * 128;
#pragma unroll
            for (int v4 = 0; v4 < 4; v4++) {
                const uint32_t sw = (uint32_t)(((2 * v4 + lk) ^ l7) << 4);
                uint32_t vb4[4];
                LDSM4T(vb4, vrow + sw);
                MMA_F16(o[2 * v4],     a0, a1, a2, a3, vb4[0], vb4[1]);
                MMA_F16(o[2 * v4 + 1], a0, a1, a2, a3, vb4[2], vb4[3]);
            }
        }

        // ---- prefetch tile it+2 into buffer s ----
        if (it + 2 < n) {
            __syncthreads();
            ldKV(it + 2, s);
        }
        CPA_COMMIT();
    }

    // ---- write fp16 output ----
    const float i0 = 1.0f / l0, i1 = 1.0f / l1;
    __half* o0 = out + (size_t)(bT + qs + w * 16 + g) * Dm + h64;
    __half* o1 = o0 + (size_t)8 * Dm;
#pragma unroll
    for (int j = 0; j < 8; j++) {
        const int col = 8 * j + 2 * l4;
        *(__half2*)(o0 + col) = __floats2half2_rn(o[j][0] * i0, o[j][1] * i0);
        *(__half2*)(o1 + col) = __floats2half2_rn(o[j][2] * i1, o[j][3] * i1);
    }
}

// ---------------- launch ----------------
extern "C" void kernel_launch(void* const* d_in, const int* in_sizes, int n_in,
                              void* d_out, int out_size)
{
    const float* x    = (const float*)d_in[0];
    const float* in_w = (const float*)d_in[1];
    const float* in_b = (const float*)d_in[2];
    const float* ow   = (const float*)d_in[3];
    const float* ob   = (const float*)d_in[4];
    const float* w1   = (const float*)d_in[5];
    const float* b1   = (const float*)d_in[6];
    const float* w2   = (const float*)d_in[7];
    const float* b2   = (const float*)d_in[8];
    const float* ln1g = (const float*)d_in[9];
    const float* ln1b = (const float*)d_in[10];
    const float* ln2g = (const float*)d_in[11];
    const float* ln2b = (const float*)d_in[12];
    float* out = (float*)d_out;

    __half *xnh, *qkvh, *attnh, *hh, *wqkvh, *owh, *w1h, *w2h;
    float* x1;
    cudaGetSymbolAddress((void**)&xnh,   g_xnh);
    cudaGetSymbolAddress((void**)&qkvh,  g_qkvh);
    cudaGetSymbolAddress((void**)&attnh, g_attnh);
    cudaGetSymbolAddress((void**)&hh,    g_hh);
    cudaGetSymbolAddress((void**)&x1,    g_x1);
    cudaGetSymbolAddress((void**)&wqkvh, g_wqkvh);
    cudaGetSymbolAddress((void**)&owh,   g_owh);
    cudaGetSymbolAddress((void**)&w1h,   g_w1h);
    cudaGetSymbolAddress((void**)&w2h,   g_w2h);

    cudaFuncSetAttribute(attn_kernel, cudaFuncAttributeMaxDynamicSharedMemorySize, SMEM_ATTN);
    cudaFuncSetAttribute(gemm_h_kernel<0, 0, 1>, cudaFuncAttributeMaxDynamicSharedMemorySize, SMEM_GEMM);
    cudaFuncSetAttribute(gemm_h_kernel<0, 1, 0>, cudaFuncAttributeMaxDynamicSharedMemorySize, SMEM_GEMM);
    cudaFuncSetAttribute(gemm_h_kernel<1, 0, 1>, cudaFuncAttributeMaxDynamicSharedMemorySize, SMEM_GEMM);

    // 0) weight conversion fp32 -> fp16
    f2h_kernel<<<(3 * Dm * Dm / 4 + 255) / 256, 256>>>(in_w, wqkvh, 3 * Dm * Dm);
    f2h_kernel<<<(Dm * Dm / 4 + 255) / 256, 256>>>(ow, owh, Dm * Dm);
    f2h_kernel<<<(MLPD * Dm / 4 + 255) / 256, 256>>>(w1, w1h, MLPD * Dm);
    f2h_kernel<<<(Dm * MLPD / 4 + 255) / 256, 256>>>(w2, w2h, Dm * MLPD);

    // 1) LN1 -> fp16
    ln_kernel<<<NT, 256>>>(x, ln1g, ln1b, xnh);
    // 2) QKV projection -> fp16
    gemm_h_kernel<0, 0, 1><<<dim3(3 * Dm / BN, NT / BM), 256, SMEM_GEMM>>>(
        xnh, wqkvh, in_b, nullptr, qkvh, NT, 3 * Dm, Dm);
    // 3) banded attention -> fp16
    attn_kernel<<<dim3(Tn / 128, Hn, Bsz), 256, SMEM_ATTN>>>(qkvh, attnh);
    // 4) out projection + residual -> fp32 x1
    gemm_h_kernel<0, 1, 0><<<dim3(Dm / BN, NT / BM), 256, SMEM_GEMM>>>(
        attnh, owh, ob, x, x1, NT, Dm, Dm);
    // 5) LN2 -> fp16
    ln_kernel<<<NT, 256>>>(x1, ln2g, ln2b, xnh);
    // 6) MLP up + GELU -> fp16
    gemm_h_kernel<1, 0, 1><<<dim3(MLPD / BN, NT / BM), 256, SMEM_GEMM>>>(
        xnh, w1h, b1, nullptr, hh, NT, MLPD, Dm);
    // 7) MLP down + residual -> fp32 d_out
    gemm_h_kernel<0, 1, 0><<<dim3(Dm / BN, NT / BM), 256, SMEM_GEMM>>>(
        hh, w2h, b2, x1, out, NT, Dm, MLPD);
}

// round 12
// speedup vs baseline: 6.3967x; 1.0311x over previous
#include <cuda_runtime.h>
#include <cuda_fp16.h>
#include <math.h>
#include <stdint.h>

#define Bsz  4
#define Tn   2048
#define Dm   768
#define Hn   12
#define HDm  64
#define MLPD 3072
#define WIN  256
#define NT   (Bsz * Tn)   /* 8192 rows */

// ---------------- static scratch ----------------
__device__ __half g_xnh  [NT * Dm];
__device__ __half g_qkvh [NT * 3 * Dm];
__device__ __half g_attnh[NT * Dm];
__device__ __half g_hh   [NT * MLPD];
__device__ float  g_x1   [NT * Dm];
__device__ __half g_wqkvh[3 * Dm * Dm];
__device__ __half g_owh  [Dm * Dm];
__device__ __half g_w1h  [MLPD * Dm];
__device__ __half g_w2h  [Dm * MLPD];

__device__ __forceinline__ uint32_t smem_u32(const void* p) {
    uint32_t a;
    asm("{ .reg .u64 t; cvta.to.shared.u64 t, %1; cvt.u32.u64 %0, t; }"
        : "=r"(a) : "l"(p));
    return a;
}

#define CPA16(dst, src) \
    asm volatile("cp.async.cg.shared.global [%0], [%1], 16;" \
                 :: "r"(dst), "l"(src) : "memory")
#define CPA_COMMIT() asm volatile("cp.async.commit_group;" ::: "memory")
#define CPA_WAIT1()  asm volatile("cp.async.wait_group 1;" ::: "memory")
#define CPA_WAIT0()  asm volatile("cp.async.wait_group 0;" ::: "memory")

#define LDSM4(r, addr)                                                        \
    asm volatile("ldmatrix.sync.aligned.m8n8.x4.shared.b16 {%0,%1,%2,%3}, [%4];" \
        : "=r"((r)[0]), "=r"((r)[1]), "=r"((r)[2]), "=r"((r)[3]) : "r"(addr))
#define LDSM4T(r, addr)                                                       \
    asm volatile("ldmatrix.sync.aligned.m8n8.x4.trans.shared.b16 {%0,%1,%2,%3}, [%4];" \
        : "=r"((r)[0]), "=r"((r)[1]), "=r"((r)[2]), "=r"((r)[3]) : "r"(addr))

#define MMA_F16(c, A0, A1, A2, A3, B0, B1)                               \
    asm volatile(                                                        \
        "mma.sync.aligned.m16n8k16.row.col.f32.f16.f16.f32 "             \
        "{%0,%1,%2,%3}, {%4,%5,%6,%7}, {%8,%9}, {%0,%1,%2,%3};"          \
        : "+f"((c)[0]), "+f"((c)[1]), "+f"((c)[2]), "+f"((c)[3])         \
        : "r"(A0), "r"(A1), "r"(A2), "r"(A3), "r"(B0), "r"(B1))

__device__ __forceinline__ uint32_t packh2(float a, float b) {
    __half2 h = __floats2half2_rn(a, b);
    return *(uint32_t*)&h;
}

// ---------------- fused fp32 -> fp16 conversion (all 4 weight tensors) ----------------
// blocks: wqkv 864 | ow 288 | w1 1152 | w2 1152  (2048 elems per block)
__global__ void __launch_bounds__(256) f2h4_kernel(
    const float* __restrict__ s0, const float* __restrict__ s1,
    const float* __restrict__ s2, const float* __restrict__ s3,
    __half* __restrict__ d0, __half* __restrict__ d1,
    __half* __restrict__ d2, __half* __restrict__ d3)
{
    int blk = blockIdx.x;
    const float* s; __half* d;
    if      (blk < 864)  { s = s0; d = d0; }
    else if (blk < 1152) { s = s1; d = d1; blk -= 864; }
    else if (blk < 2304) { s = s2; d = d2; blk -= 1152; }
    else                 { s = s3; d = d3; blk -= 2304; }
    const int i = blk * 2048 + threadIdx.x * 8;
    const float4 a = *(const float4*)(s + i);
    const float4 b = *(const float4*)(s + i + 4);
    *(__half2*)(d + i)     = __floats2half2_rn(a.x, a.y);
    *(__half2*)(d + i + 2) = __floats2half2_rn(a.z, a.w);
    *(__half2*)(d + i + 4) = __floats2half2_rn(b.x, b.y);
    *(__half2*)(d + i + 6) = __floats2half2_rn(b.z, b.w);
}

// ---------------- LayerNorm (fp32 in -> fp16 out), float4 vectorized ----------------
__global__ void __launch_bounds__(192) ln_kernel(const float* __restrict__ x,
                                                 const float* __restrict__ g,
                                                 const float* __restrict__ b,
                                                 __half* __restrict__ y)
{
    const int row = blockIdx.x;
    const int t = threadIdx.x;
    const float4 v = *(const float4*)(x + (size_t)row * Dm + t * 4);

    float s  = v.x + v.y + v.z + v.w;
    float s2 = v.x * v.x + v.y * v.y + v.z * v.z + v.w * v.w;
    __shared__ float red[12];
#pragma unroll
    for (int o = 16; o > 0; o >>= 1) {
        s  += __shfl_xor_sync(0xffffffffu, s,  o);
        s2 += __shfl_xor_sync(0xffffffffu, s2, o);
    }
    const int w = t >> 5;
    if ((t & 31) == 0) { red[w] = s; red[6 + w] = s2; }
    __syncthreads();
    s = 0.f; s2 = 0.f;
#pragma unroll
    for (int i = 0; i < 6; i++) { s += red[i]; s2 += red[6 + i]; }

    const float mean = s * (1.0f / Dm);
    float var = s2 * (1.0f / Dm) - mean * mean;
    var = fmaxf(var, 0.0f);
    const float rstd = rsqrtf(var + 1e-5f);

    const float4 g4 = *(const float4*)(g + t * 4);
    const float4 b4 = *(const float4*)(b + t * 4);
    __half* yr = y + (size_t)row * Dm + t * 4;
    *(__half2*)(yr)     = __floats2half2_rn((v.x - mean) * rstd * g4.x + b4.x,
                                            (v.y - mean) * rstd * g4.y + b4.y);
    *(__half2*)(yr + 2) = __floats2half2_rn((v.z - mean) * rstd * g4.z + b4.z,
                                            (v.w - mean) * rstd * g4.w + b4.w);
}

// ---------------- fp16 GEMM: cp.async + ldmatrix + mma.m16n8k16 ----------------
// C[M,N] = A[M,K] @ B[N,K]^T + bias (+res) (+gelu). TBM = 128 or 64.
#define BN 128
#define BKH 64
#define STAGES 3
#define BSTG 16384

template<int GELU, int RES, int OUTH, int TBM>
__global__ void __launch_bounds__(256, 2) gemm_h_kernel(
    const __half* __restrict__ A,
    const __half* __restrict__ B,
    const float* __restrict__ bias,
    const float* __restrict__ res,
    void* __restrict__ Cv,
    int M, int N, int K)
{
    constexpr int WROWS = TBM / 2;       // rows per M-warp group
    constexpr int MT    = WROWS / 16;    // m16 tiles per warp (4 or 2)
    constexpr int AIT   = TBM / 32;      // cp.async row iterations for A
    constexpr int ASTG  = TBM * 128;     // bytes per A stage

    extern __shared__ char sh[];
    const uint32_t sA = smem_u32(sh);
    const uint32_t sB = sA + STAGES * ASTG;

    const int t    = threadIdx.x;
    const int lane = t & 31;
    const int warp = t >> 5;
    const int wm   = warp & 1;
    const int wn   = warp >> 1;
    const int bm   = blockIdx.y * TBM;
    const int bn   = blockIdx.x * BN;

    const int cm  = t >> 3;
    const int ckq = t & 7;
    const uint32_t daBase = cm * 128 + (uint32_t)((ckq ^ (cm & 7)) << 4);
    const __half* Ag = A + (size_t)(bm + cm) * K + ckq * 8;
    const __half* Bg = B + (size_t)(bn + cm) * K + ckq * 8;

    const int l15 = lane & 15;
    const int lk  = lane >> 4;
    const int l7  = lane & 7;
    uint32_t aoff[MT], boff[2];
#pragma unroll
    for (int mt = 0; mt < MT; mt++) aoff[mt] = (uint32_t)((wm * WROWS + mt * 16 + l15) * 128);
#pragma unroll
    for (int n2 = 0; n2 < 2; n2++) boff[n2] = (uint32_t)((wn * 32 + n2 * 16 + l15) * 128);

    float acc[MT][4][4];
#pragma unroll
    for (int mt = 0; mt < MT; mt++)
#pragma unroll
        for (int nt = 0; nt < 4; nt++)
#pragma unroll
            for (int q = 0; q < 4; q++) acc[mt][nt][q] = 0.f;

    const int nch = K / BKH;

    auto issue = [&](int ch, int s) {
        const __half* ag = Ag + ch * BKH;
        const __half* bg = Bg + ch * BKH;
        const uint32_t da = sA + s * ASTG + daBase;
        const uint32_t db = sB + s * BSTG + daBase;
#pragma unroll
        for (int i = 0; i < AIT; i++)
            CPA16(da + i * 32 * 128, ag + (size_t)i * 32 * K);
#pragma unroll
        for (int i = 0; i < 4; i++)
            CPA16(db + i * 32 * 128, bg + (size_t)i * 32 * K);
    };

    issue(0, 0); CPA_COMMIT();
    issue(1, 1); CPA_COMMIT();

    for (int ch = 0; ch < nch; ch++) {
        CPA_WAIT1();
        __syncthreads();
        if (ch + 2 < nch) issue(ch + 2, (ch + 2) % STAGES);
        CPA_COMMIT();

        const uint32_t baA = sA + (ch % STAGES) * ASTG;
        const uint32_t baB = sB + (ch % STAGES) * BSTG;
#pragma unroll
        for (int ks = 0; ks < 4; ks++) {
            const uint32_t sw = (uint32_t)(((2 * ks + lk) ^ l7) << 4);
            uint32_t a[MT][4], b[2][4];
#pragma unroll
            for (int mt = 0; mt < MT; mt++) LDSM4(a[mt], baA + aoff[mt] + sw);
#pragma unroll
            for (int n2 = 0; n2 < 2; n2++) LDSM4(b[n2], baB + boff[n2] + sw);
#pragma unroll
            for (int mt = 0; mt < MT; mt++)
#pragma unroll
                for (int nt = 0; nt < 4; nt++)
                    MMA_F16(acc[mt][nt],
                            a[mt][0], a[mt][1], a[mt][2], a[mt][3],
                            b[nt >> 1][nt & 1], b[nt >> 1][2 + (nt & 1)]);
        }
    }

    // ---- epilogue ----
    const int g  = lane >> 2;
    const int l4 = lane & 3;
#pragma unroll
    for (int mt = 0; mt < MT; mt++) {
        const int r0 = bm + wm * WROWS + mt * 16 + g;
#pragma unroll
        for (int nt = 0; nt < 4; nt++) {
            const int col = bn + wn * 32 + nt * 8 + l4 * 2;
            const float2 bia = *(const float2*)(bias + col);
            float v00 = acc[mt][nt][0] + bia.x, v01 = acc[mt][nt][1] + bia.y;
            float v10 = acc[mt][nt][2] + bia.x, v11 = acc[mt][nt][3] + bia.y;
            if (RES) {
                const float2 q0 = *(const float2*)(res + (size_t)r0 * N + col);
                const float2 q1 = *(const float2*)(res + (size_t)(r0 + 8) * N + col);
                v00 += q0.x; v01 += q0.y; v10 += q1.x; v11 += q1.y;
            }
            if (GELU) {
                v00 = 0.5f * v00 * (1.0f + erff(v00 * 0.70710678118654752f));
                v01 = 0.5f * v01 * (1.0f + erff(v01 * 0.70710678118654752f));
                v10 = 0.5f * v10 * (1.0f + erff(v10 * 0.70710678118654752f));
                v11 = 0.5f * v11 * (1.0f + erff(v11 * 0.70710678118654752f));
            }
            if (OUTH) {
                __half* Ch = (__half*)Cv;
                *(__half2*)(Ch + (size_t)r0 * N + col)       = __floats2half2_rn(v00, v01);
                *(__half2*)(Ch + (size_t)(r0 + 8) * N + col) = __floats2half2_rn(v10, v11);
            } else {
                float* Cf = (float*)Cv;
                *(float2*)(Cf + (size_t)r0 * N + col)       = make_float2(v00, v01);
                *(float2*)(Cf + (size_t)(r0 + 8) * N + col) = make_float2(v10, v11);
            }
        }
    }
}

// ---------------- banded flash attention (fp16 mma, __expf softmax) ----------------
#define SATT_Q 0
#define SATT_K 16384
#define SATT_V 32768
#define SMEM_ATTN 49152

__global__ void __launch_bounds__(256, 2) attn_kernel(const __half* __restrict__ qkv,
                                                      __half* __restrict__ out)
{
    extern __shared__ char shm[];
    const uint32_t sbase = smem_u32(shm);
    const uint32_t sQ = sbase + SATT_Q;
    const uint32_t sK = sbase + SATT_K;
    const uint32_t sV = sbase + SATT_V;

    const int t    = threadIdx.x;
    const int lane = t & 31;
    const int w    = t >> 5;
    const int qs   = blockIdx.x * 128;
    const int h    = blockIdx.y;
    const int b    = blockIdx.z;
    const int bT   = b * Tn;
    const int h64  = h * HDm;

    const int l15 = lane & 15;
    const int lk  = lane >> 4;
    const int l7  = lane & 7;
    const int g   = lane >> 2;
    const int l4  = lane & 3;
    const int trow = ((lane >> 3) & 1) * 8 + (lane & 7);

    const int kt0 = (qs - WIN > 0) ? qs - WIN : 0;
    const int kt1 = (qs + 128 + WIN < Tn) ? qs + 128 + WIN : Tn;
    const int n   = (kt1 - kt0) >> 6;

    auto ldQ = [&]() {
#pragma unroll
        for (int i = 0; i < 4; i++) {
            const int idx = t + i * 256;
            const int r = idx >> 3, c = idx & 7;
            CPA16(sQ + r * 128 + ((c ^ (r & 7)) << 4),
                  qkv + (size_t)(bT + qs + r) * 2304 + h64 + c * 8);
        }
    };
    auto ldKV = [&](int tile, int s) {
#pragma unroll
        for (int i = 0; i < 2; i++) {
            const int idx = t + i * 256;
            const int key = idx >> 3, c = idx & 7;
            const uint32_t off = s * 8192 + key * 128 + ((c ^ (key & 7)) << 4);
            const __half* src = qkv + (size_t)(bT + kt0 + tile * 64 + key) * 2304 + h64 + c * 8;
            CPA16(sK + off, src + Dm);
            CPA16(sV + off, src + 2 * Dm);
        }
    };

    ldQ(); ldKV(0, 0); CPA_COMMIT();
    if (n > 1) ldKV(1, 1);
    CPA_COMMIT();

    float o[8][4];
#pragma unroll
    for (int j = 0; j < 8; j++)
#pragma unroll
        for (int q = 0; q < 4; q++) o[j][q] = 0.f;
    float m0 = -1e30f, m1 = -1e30f, l0 = 0.f, l1 = 0.f;

    const int qmin = qs + w * 16;
    const int q0 = qmin + g, q1 = q0 + 8;
    const uint32_t qb = sQ + (w * 16 + l15) * 128;

    for (int it = 0; it < n; it++) {
        const int s  = it & 1;
        const int kt = kt0 + it * 64;

        if (it + 1 < n) CPA_WAIT1(); else CPA_WAIT0();
        __syncthreads();

        // ---- S = Q @ K^T ----
        float sc[8][4];
#pragma unroll
        for (int j = 0; j < 8; j++)
#pragma unroll
            for (int q = 0; q < 4; q++) sc[j][q] = 0.f;

        const uint32_t kb_ = sK + s * 8192;
#pragma unroll
        for (int ks = 0; ks < 4; ks++) {
            const uint32_t sw = (uint32_t)(((2 * ks + lk) ^ l7) << 4);
            uint32_t qa[4];
            LDSM4(qa, qb + sw);
#pragma unroll
            for (int j2 = 0; j2 < 4; j2++) {
                uint32_t kb4[4];
                LDSM4(kb4, kb_ + (j2 * 16 + l15) * 128 + sw);
                MMA_F16(sc[2 * j2],     qa[0], qa[1], qa[2], qa[3], kb4[0], kb4[2]);
                MMA_F16(sc[2 * j2 + 1], qa[0], qa[1], qa[2], qa[3], kb4[1], kb4[3]);
            }
        }

        // ---- scale + band mask + online softmax ----
        const bool full = (kt >= qmin + 15 - WIN) && (kt + 63 <= qmin + WIN);
        float tm0 = -2e30f, tm1 = -2e30f;
#pragma unroll
        for (int j = 0; j < 8; j++) {
#pragma unroll
            for (int q = 0; q < 4; q++) sc[j][q] *= 0.125f;
            if (!full) {
                const int kc = kt + 8 * j + 2 * l4;
                if (q0 - kc > WIN || kc - q0 > WIN)         sc[j][0] = -2e30f;
                if (q0 - kc - 1 > WIN || kc + 1 - q0 > WIN) sc[j][1] = -2e30f;
                if (q1 - kc > WIN || kc - q1 > WIN)         sc[j][2] = -2e30f;
                if (q1 - kc - 1 > WIN || kc + 1 - q1 > WIN) sc[j][3] = -2e30f;
            }
            tm0 = fmaxf(tm0, fmaxf(sc[j][0], sc[j][1]));
            tm1 = fmaxf(tm1, fmaxf(sc[j][2], sc[j][3]));
        }
        tm0 = fmaxf(tm0, __shfl_xor_sync(0xffffffffu, tm0, 1));
        tm0 = fmaxf(tm0, __shfl_xor_sync(0xffffffffu, tm0, 2));
        tm1 = fmaxf(tm1, __shfl_xor_sync(0xffffffffu, tm1, 1));
        tm1 = fmaxf(tm1, __shfl_xor_sync(0xffffffffu, tm1, 2));

        const float m0n = fmaxf(m0, tm0), m1n = fmaxf(m1, tm1);
        const float f0 = __expf(m0 - m0n), f1 = __expf(m1 - m1n);
        float s0 = 0.f, s1 = 0.f;
#pragma unroll
        for (int j = 0; j < 8; j++) {
            sc[j][0] = __expf(sc[j][0] - m0n);
            sc[j][1] = __expf(sc[j][1] - m0n);
            sc[j][2] = __expf(sc[j][2] - m1n);
            sc[j][3] = __expf(sc[j][3] - m1n);
            s0 += sc[j][0] + sc[j][1];
            s1 += sc[j][2] + sc[j][3];
        }
        s0 += __shfl_xor_sync(0xffffffffu, s0, 1);
        s0 += __shfl_xor_sync(0xffffffffu, s0, 2);
        s1 += __shfl_xor_sync(0xffffffffu, s1, 1);
        s1 += __shfl_xor_sync(0xffffffffu, s1, 2);
        l0 = l0 * f0 + s0;
        l1 = l1 * f1 + s1;
        m0 = m0n; m1 = m1n;
#pragma unroll
        for (int j = 0; j < 8; j++) {
            o[j][0] *= f0; o[j][1] *= f0; o[j][2] *= f1; o[j][3] *= f1;
        }

        // ---- O += P @ V ----
        const uint32_t vb_ = sV + s * 8192;
#pragma unroll
        for (int j2 = 0; j2 < 4; j2++) {
            const uint32_t a0 = packh2(sc[2 * j2][0],     sc[2 * j2][1]);
            const uint32_t a1 = packh2(sc[2 * j2][2],     sc[2 * j2][3]);
            const uint32_t a2 = packh2(sc[2 * j2 + 1][0], sc[2 * j2 + 1][1]);
            const uint32_t a3 = packh2(sc[2 * j2 + 1][2], sc[2 * j2 + 1][3]);
            const uint32_t vrow = vb_ + (j2 * 16 + trow) * 128;
#pragma unroll
            for (int v4 = 0; v4 < 4; v4++) {
                const uint32_t sw = (uint32_t)(((2 * v4 + lk) ^ l7) << 4);
                uint32_t vb4[4];
                LDSM4T(vb4, vrow + sw);
                MMA_F16(o[2 * v4],     a0, a1, a2, a3, vb4[0], vb4[1]);
                MMA_F16(o[2 * v4 + 1], a0, a1, a2, a3, vb4[2], vb4[3]);
            }
        }

        if (it + 2 < n) {
            __syncthreads();
            ldKV(it + 2, s);
        }
        CPA_COMMIT();
    }

    // ---- write fp16 output ----
    const float i0 = 1.0f / l0, i1 = 1.0f / l1;
    __half* o0 = out + (size_t)(bT + qs + w * 16 + g) * Dm + h64;
    __half* o1 = o0 + (size_t)8 * Dm;
#pragma unroll
    for (int j = 0; j < 8; j++) {
        const int col = 8 * j + 2 * l4;
        *(__half2*)(o0 + col) = __floats2half2_rn(o[j][0] * i0, o[j][1] * i0);
        *(__half2*)(o1 + col) = __floats2half2_rn(o[j][2] * i1, o[j][3] * i1);
    }
}

// ---------------- launch ----------------
extern "C" void kernel_launch(void* const* d_in, const int* in_sizes, int n_in,
                              void* d_out, int out_size)
{
    const float* x    = (const float*)d_in[0];
    const float* in_w = (const float*)d_in[1];
    const float* in_b = (const float*)d_in[2];
    const float* ow   = (const float*)d_in[3];
    const float* ob   = (const float*)d_in[4];
    const float* w1   = (const float*)d_in[5];
    const float* b1   = (const float*)d_in[6];
    const float* w2   = (const float*)d_in[7];
    const float* b2   = (const float*)d_in[8];
    const float* ln1g = (const float*)d_in[9];
    const float* ln1b = (const float*)d_in[10];
    const float* ln2g = (const float*)d_in[11];
    const float* ln2b = (const float*)d_in[12];
    float* out = (float*)d_out;

    __half *xnh, *qkvh, *attnh, *hh, *wqkvh, *owh, *w1h, *w2h;
    float* x1;
    cudaGetSymbolAddress((void**)&xnh,   g_xnh);
    cudaGetSymbolAddress((void**)&qkvh,  g_qkvh);
    cudaGetSymbolAddress((void**)&attnh, g_attnh);
    cudaGetSymbolAddress((void**)&hh,    g_hh);
    cudaGetSymbolAddress((void**)&x1,    g_x1);
    cudaGetSymbolAddress((void**)&wqkvh, g_wqkvh);
    cudaGetSymbolAddress((void**)&owh,   g_owh);
    cudaGetSymbolAddress((void**)&w1h,   g_w1h);
    cudaGetSymbolAddress((void**)&w2h,   g_w2h);

    const int SMEM128 = STAGES * (128 * 128 + BSTG);  // 98304
    const int SMEM64  = STAGES * (64 * 128 + BSTG);   // 73728

    cudaFuncSetAttribute(attn_kernel, cudaFuncAttributeMaxDynamicSharedMemorySize, SMEM_ATTN);
    cudaFuncSetAttribute(gemm_h_kernel<0, 0, 1, 128>, cudaFuncAttributeMaxDynamicSharedMemorySize, SMEM128);
    cudaFuncSetAttribute(gemm_h_kernel<1, 0, 1, 128>, cudaFuncAttributeMaxDynamicSharedMemorySize, SMEM128);
    cudaFuncSetAttribute(gemm_h_kernel<0, 1, 0, 64>,  cudaFuncAttributeMaxDynamicSharedMemorySize, SMEM64);

    // 0) fused weight conversion fp32 -> fp16
    f2h4_kernel<<<3456, 256>>>(in_w, ow, w1, w2, wqkvh, owh, w1h, w2h);

    // 1) LN1 -> fp16
    ln_kernel<<<NT, 192>>>(x, ln1g, ln1b, xnh);
    // 2) QKV projection -> fp16
    gemm_h_kernel<0, 0, 1, 128><<<dim3(3 * Dm / BN, NT / 128), 256, SMEM128>>>(
        xnh, wqkvh, in_b, nullptr, qkvh, NT, 3 * Dm, Dm);
    // 3) banded attention -> fp16
    attn_kernel<<<dim3(Tn / 128, Hn, Bsz), 256, SMEM_ATTN>>>(qkvh, attnh);
    // 4) out projection + residual -> fp32 x1  (BM=64: less wave tail)
    gemm_h_kernel<0, 1, 0, 64><<<dim3(Dm / BN, NT / 64), 256, SMEM64>>>(
        attnh, owh, ob, x, x1, NT, Dm, Dm);
    // 5) LN2 -> fp16
    ln_kernel<<<NT, 192>>>(x1, ln2g, ln2b, xnh);
    // 6) MLP up + GELU -> fp16
    gemm_h_kernel<1, 0, 1, 128><<<dim3(MLPD / BN, NT / 128), 256, SMEM128>>>(
        xnh, w1h, b1, nullptr, hh, NT, MLPD, Dm);
    // 7) MLP down + residual -> fp32 d_out  (BM=64)
    gemm_h_kernel<0, 1, 0, 64><<<dim3(Dm / BN, NT / 64), 256, SMEM64>>>(
        hh, w2h, b2, x1, out, NT, Dm, MLPD);
}